// round 9
// baseline (speedup 1.0000x reference)
#include <cuda_runtime.h>
#include <cuda_fp16.h>
#include <float.h>
#include <stdint.h>

#define Bsz  8
#define Cdim 128
#define Ndim 4096
#define Odim 256
#define KNN  16
#define NCAND 40
#define FULLM 0xFFFFFFFFu

// ---------------- scratch (static device globals; no allocations) -------------
__device__ float g_net[Bsz * Cdim * Ndim];     // [b][c][n]      16 MB
__device__ float g_sq[Bsz * Ndim];             // [b][n]
__device__ int   g_idx[Bsz * Ndim * KNN];      // [b][n][k]       2 MB
__device__ float g_p1t[Bsz * Ndim * Odim];     // [b][n][o]      32 MB
__device__ float g_baset[Bsz * Ndim * Odim];   // [b][n][o]      32 MB
__device__ __half g_hi[Bsz * Ndim * Cdim];     // [b][n][c]       8 MB
__device__ float g_netT[Bsz * Ndim * Cdim];    // [b][n][c]      16 MB
__device__ int   g_cand[Bsz * Ndim * NCAND];   // coarse candidate indices

__device__ __forceinline__ uint32_t smem_u32(const void* p) {
    uint32_t a;
    asm("{ .reg .u64 t; cvta.to.shared.u64 t, %1; cvt.u32.u64 %0, t; }" : "=r"(a) : "l"(p));
    return a;
}
__device__ __forceinline__ void ldmx4(uint32_t* r, uint32_t addr) {
    asm volatile("ldmatrix.sync.aligned.m8n8.x4.shared.b16 {%0,%1,%2,%3}, [%4];"
        : "=r"(r[0]), "=r"(r[1]), "=r"(r[2]), "=r"(r[3]) : "r"(addr));
}
__device__ __forceinline__ void mma16816(float* c, const uint32_t* a,
                                         uint32_t b0, uint32_t b1) {
    asm volatile("mma.sync.aligned.m16n8k16.row.col.f32.f16.f16.f32 "
        "{%0,%1,%2,%3}, {%4,%5,%6,%7}, {%8,%9}, {%0,%1,%2,%3};"
        : "+f"(c[0]), "+f"(c[1]), "+f"(c[2]), "+f"(c[3])
        : "r"(a[0]), "r"(a[1]), "r"(a[2]), "r"(a[3]), "r"(b0), "r"(b1));
}

// ==============================================================================
// Kernel A: net = relu(w0 @ x + b0), fused sq[b][n] = sum_c net^2
// ==============================================================================
__global__ __launch_bounds__(256) void k_net(const float* __restrict__ x,
                                             const float* __restrict__ w0,
                                             const float* __restrict__ b0) {
    __shared__ float Ws[32][129];
    __shared__ float Ns[32][128];
    __shared__ float sqs[16][129];

    const int b  = blockIdx.y;
    const int n0 = blockIdx.x * 128;
    const int tid = threadIdx.x;
    const int tx = tid & 15;
    const int ty = tid >> 4;

    float acc[8][8];
    #pragma unroll
    for (int i = 0; i < 8; ++i)
        #pragma unroll
        for (int j = 0; j < 8; ++j) acc[i][j] = 0.f;

    for (int k0 = 0; k0 < 128; k0 += 32) {
        __syncthreads();
        #pragma unroll
        for (int i = 0; i < 16; ++i) {
            int idx = tid + i * 256;
            int cc = idx & 31, o = idx >> 5;
            Ws[cc][o] = w0[o * 128 + k0 + cc];
        }
        #pragma unroll
        for (int i = 0; i < 16; ++i) {
            int idx = tid + i * 256;
            int c = idx >> 7, n = idx & 127;
            Ns[c][n] = x[(b * 128 + k0 + c) * Ndim + n0 + n];
        }
        __syncthreads();
        #pragma unroll
        for (int kk = 0; kk < 32; ++kk) {
            float4 x0 = *(const float4*)&Ns[kk][tx * 8];
            float4 x1 = *(const float4*)&Ns[kk][tx * 8 + 4];
            float xr[8] = {x0.x, x0.y, x0.z, x0.w, x1.x, x1.y, x1.z, x1.w};
            #pragma unroll
            for (int i = 0; i < 8; ++i) {
                float wv = Ws[kk][ty * 8 + i];
                #pragma unroll
                for (int j = 0; j < 8; ++j) acc[i][j] += wv * xr[j];
            }
        }
    }

    float part[8];
    #pragma unroll
    for (int j = 0; j < 8; ++j) part[j] = 0.f;

    #pragma unroll
    for (int i = 0; i < 8; ++i) {
        int o = ty * 8 + i;
        float bv = __ldg(&b0[o]);
        float r[8];
        #pragma unroll
        for (int j = 0; j < 8; ++j) {
            r[j] = fmaxf(acc[i][j] + bv, 0.f);
            part[j] += r[j] * r[j];
        }
        int base = (b * 128 + o) * Ndim + n0 + tx * 8;
        float4 s0 = {r[0], r[1], r[2], r[3]};
        float4 s1 = {r[4], r[5], r[6], r[7]};
        *(float4*)&g_net[base]     = s0;
        *(float4*)&g_net[base + 4] = s1;
    }
    #pragma unroll
    for (int j = 0; j < 8; ++j) sqs[ty][tx * 8 + j] = part[j];
    __syncthreads();
    if (tid < 128) {
        float s = 0.f;
        #pragma unroll
        for (int r = 0; r < 16; ++r) s += sqs[r][tid];
        g_sq[b * Ndim + n0 + tid] = s;
    }
}

// ==============================================================================
// Kernel B: transpose: g_net[b][c][n] -> g_hi (fp16) and g_netT (fp32), [b][n][c]
// ==============================================================================
__global__ __launch_bounds__(256) void k_split() {
    __shared__ float s[32][33];
    const int b  = blockIdx.z;
    const int c0 = blockIdx.y * 32;
    const int n0 = blockIdx.x * 32;
    const int tx = threadIdx.x & 31;
    const int ty = threadIdx.x >> 5;    // 0..7

    #pragma unroll
    for (int i = 0; i < 4; ++i) {
        int c = ty + i * 8;
        s[c][tx] = g_net[(b * Cdim + c0 + c) * Ndim + n0 + tx];
    }
    __syncthreads();
    #pragma unroll
    for (int i = 0; i < 4; ++i) {
        int nl = ty + i * 8;
        float v = s[tx][nl];
        int dst = (b * Ndim + n0 + nl) * Cdim + c0 + tx;
        g_hi[dst]   = __float2half(v);
        g_netT[dst] = v;
    }
}

// ==============================================================================
// Kernel C v9: coarse kNN. 1-pass fp16 gram, R6-verified keys tile + per-query
// (threads 0..127) branchless register top-40 -> g_cand indices.
// grid (32, 8), 256 threads (8 warps). M-tile = 128.
// ==============================================================================
#define PITCHB 272                     // 136 halves/row: conflict-free ldmatrix
#define TILEB  (128 * PITCHB)          // 34816 B per 128x128 fp16 tile
#define SM_QHI 0
#define SM_MHI TILEB
#define SM_KEY (2 * TILEB)             // 128 x 132 floats = 67584 B
#define SM_SQM (SM_KEY + 128 * 132 * 4)
#define SM_TOT (SM_SQM + 512)

__device__ __forceinline__ void load_tile16(char* smem, uint32_t dst,
                                            const __half* __restrict__ src) {
    for (int i = threadIdx.x; i < 2048; i += 256) {
        int row = i >> 4, c8 = (i & 15) * 8;
        uint4 v = *(const uint4*)(src + row * Cdim + c8);
        *(uint4*)(smem + dst + row * PITCHB + c8 * 2) = v;
    }
}

// Branchless sorted insert (registers, static indices). Caller: d < kd[39].
__device__ __forceinline__ void ins40(float (&kd)[NCAND], int (&ki)[NCAND],
                                      float d, int m) {
    int r = 0;
    #pragma unroll
    for (int i = 0; i < NCAND; ++i) r += (kd[i] <= d) ? 1 : 0;
    #pragma unroll
    for (int j = NCAND - 1; j > 0; --j) {
        bool sh = (j > r);
        kd[j] = sh ? kd[j - 1] : kd[j];
        ki[j] = sh ? ki[j - 1] : ki[j];
    }
    #pragma unroll
    for (int j = 0; j < NCAND; ++j)
        if (j == r) { kd[j] = d; ki[j] = m; }
}

__global__ __launch_bounds__(256, 1) void k_knn() {
    extern __shared__ char smem[];
    const uint32_t sbase = smem_u32(smem);
    const int tid  = threadIdx.x;
    const int lane = tid & 31;
    const int wid  = tid >> 5;          // 0..7
    const int b    = blockIdx.y;
    const int n0   = blockIdx.x * 128;
    const int qbase = wid * 16;

    // Stage Q hi tile (128 x 128 fp16) once
    load_tile16(smem, SM_QHI, g_hi + (size_t)(b * Ndim + n0) * Cdim);

    const uint32_t a_base = sbase + SM_QHI + (qbase + (lane & 15)) * PITCHB + ((lane >> 4) << 4);
    const uint32_t b_base = sbase + SM_MHI + ((lane & 7) + ((lane >> 4) << 3)) * PITCHB
                                  + (((lane >> 3) & 1) << 4);

    float* keysp = (float*)(smem + SM_KEY);
    const float* sqm = (const float*)(smem + SM_SQM);

    float kd[NCAND]; int ki[NCAND];
    #pragma unroll
    for (int i = 0; i < NCAND; ++i) { kd[i] = FLT_MAX; ki[i] = 0; }

    for (int mt = 0; mt < 32; ++mt) {
        const int m0 = mt * 128;
        __syncthreads();   // previous scan done; M tile + keys reusable
        load_tile16(smem, SM_MHI, g_hi + (size_t)(b * Ndim + m0) * Cdim);
        if (tid < 128) ((float*)(smem + SM_SQM))[tid] = g_sq[b * Ndim + m0 + tid];
        __syncthreads();

        float c[16][4];
        #pragma unroll
        for (int t = 0; t < 16; ++t)
            #pragma unroll
            for (int e = 0; e < 4; ++e) c[t][e] = 0.f;

        #pragma unroll
        for (int ks = 0; ks < 8; ++ks) {
            uint32_t ra[4];
            ldmx4(ra, a_base + ks * 32);
            #pragma unroll
            for (int tp = 0; tp < 8; ++tp) {
                uint32_t rb[4];
                ldmx4(rb, b_base + tp * (16 * PITCHB) + ks * 32);
                mma16816(c[2 * tp],     ra, rb[0], rb[1]);
                mma16816(c[2 * tp + 1], ra, rb[2], rb[3]);
            }
        }

        // keys[q][m] = sq[m] - 2*dot  (unpacked, R6-verified layout)
        const int q0 = qbase + (lane >> 2);
        const int mo = (lane & 3) * 2;
        #pragma unroll
        for (int t = 0; t < 16; ++t) {
            int m = t * 8 + mo;
            float s0 = sqm[m], s1 = sqm[m + 1];
            *(float2*)&keysp[q0 * 132 + m] =
                make_float2(s0 - 2.f * c[t][0], s1 - 2.f * c[t][1]);
            *(float2*)&keysp[(q0 + 8) * 132 + m] =
                make_float2(s0 - 2.f * c[t][2], s1 - 2.f * c[t][3]);
        }
        __syncthreads();

        // coarse scan: threads 0..127, one query each (R6-verified structure)
        if (tid < 128) {
            const float* krow = keysp + tid * 132;
            #pragma unroll 4
            for (int m = 0; m < 128; ++m) {
                float kv = krow[m];
                if (kv < kd[NCAND - 1]) ins40(kd, ki, kv, m0 + m);
            }
        }
    }

    if (tid < 128) {
        int* crow = g_cand + ((size_t)(b * Ndim + n0 + tid)) * NCAND;
        #pragma unroll
        for (int i = 0; i < NCAND; ++i) crow[i] = ki[i];
    }
}

// ==============================================================================
// Kernel C2: exact fp32 rescore of 40 candidates/query + exact top-17 extract.
// grid (Ndim/8, Bsz), 256 threads: warp w handles query blockIdx.x*8 + w.
// Entries 32..39 are 4x lane-duplicated; dups are killed jointly.
// ==============================================================================
__global__ __launch_bounds__(256) void k_resc() {
    const int lane = threadIdx.x & 31;
    const int wid  = threadIdx.x >> 5;
    const int b    = blockIdx.y;
    const int q    = blockIdx.x * 8 + wid;

    const float4 qv = *(const float4*)&g_netT[(size_t)(b * Ndim + q) * Cdim + lane * 4];
    const int* crow = g_cand + ((size_t)(b * Ndim + q)) * NCAND;
    int ma = crow[lane];                // entries 0..31
    int mb = crow[32 + (lane & 7)];     // entries 32..39 (4x dup)

    float part[NCAND];
    #pragma unroll
    for (int ci = 0; ci < NCAND; ++ci) {
        int m = __shfl_sync(FULLM, (ci < 32) ? ma : mb, (ci < 32) ? ci : (ci - 32));
        float4 mv = *(const float4*)&g_netT[(size_t)(b * Ndim + m) * Cdim + lane * 4];
        part[ci] = qv.x * mv.x + qv.y * mv.y + qv.z * mv.z + qv.w * mv.w;
    }
    #pragma unroll
    for (int ci = 0; ci < NCAND; ++ci) {
        float v = part[ci];
        v += __shfl_xor_sync(FULLM, v, 16);
        v += __shfl_xor_sync(FULLM, v, 8);
        v += __shfl_xor_sync(FULLM, v, 4);
        v += __shfl_xor_sync(FULLM, v, 2);
        v += __shfl_xor_sync(FULLM, v, 1);
        part[ci] = v;
    }
    float da = 0.f, db = 0.f;
    #pragma unroll
    for (int ci = 0; ci < 32; ++ci) da = (ci == lane) ? part[ci] : da;
    #pragma unroll
    for (int ci = 32; ci < NCAND; ++ci) db = ((ci - 32) == (lane & 7)) ? part[ci] : db;

    float ka = __ldg(&g_sq[b * Ndim + ma]) - 2.f * da;
    float kb = __ldg(&g_sq[b * Ndim + mb]) - 2.f * db;

    int* orow = g_idx + ((size_t)(b * Ndim + q)) * KNN;
    #pragma unroll 1
    for (int t = 0; t < 17; ++t) {
        bool sa = (ka < kb) || (ka == kb && ma < mb);
        float lk = sa ? ka : kb;
        int   lm = sa ? ma : mb;
        #pragma unroll
        for (int d = 16; d > 0; d >>= 1) {
            float ok = __shfl_xor_sync(FULLM, lk, d);
            int   om = __shfl_xor_sync(FULLM, lm, d);
            bool take = (ok < lk) || (ok == lk && om < lm);
            lk = take ? ok : lk;
            lm = take ? om : lm;
        }
        if (t > 0 && lane == 0) orow[t - 1] = lm;   // t=0 = self (strict min) dropped
        if (ma == lm) ka = FLT_MAX;
        if (mb == lm) kb = FLT_MAX;
    }
}

// ==============================================================================
// Kernel D: two independent 64-reg GEMMs selected by z&1:
//   which=0: p1   = w1@net                  -> g_p1t  [b][n][o]
//   which=1: base = (w2-w1)@net + (b1+b2)   -> g_baset[b][n][o]
// ==============================================================================
__global__ __launch_bounds__(256) void k_proj(const float* __restrict__ w1,
                                              const float* __restrict__ b1,
                                              const float* __restrict__ w2,
                                              const float* __restrict__ b2) {
    __shared__ float Wc[16][129];   // [c-chunk][o]
    __shared__ float Ns[16][128];   // [c-chunk][n]

    const int b     = blockIdx.y;
    const int n0    = blockIdx.x * 128;
    const int which = blockIdx.z & 1;
    const int oz    = (blockIdx.z >> 1) * 128;
    const int tid = threadIdx.x;
    const int tx = tid & 15;        // o group
    const int ty = tid >> 4;        // n group

    float a[8][8];
    #pragma unroll
    for (int j = 0; j < 8; ++j)
        #pragma unroll
        for (int i = 0; i < 8; ++i) a[j][i] = 0.f;

    for (int k0 = 0; k0 < 128; k0 += 16) {
        __syncthreads();
        #pragma unroll
        for (int i = 0; i < 8; ++i) {
            int idx = tid + i * 256;
            int cc = idx & 15, o = idx >> 4;
            float wv = w1[(oz + o) * 128 + k0 + cc];
            if (which) wv = w2[(oz + o) * 128 + k0 + cc] - wv;
            Wc[cc][o] = wv;
        }
        #pragma unroll
        for (int i = 0; i < 8; ++i) {
            int idx = tid + i * 256;
            int c = idx >> 7, n = idx & 127;
            Ns[c][n] = g_net[(b * 128 + k0 + c) * Ndim + n0 + n];
        }
        __syncthreads();
        #pragma unroll
        for (int kk = 0; kk < 16; ++kk) {
            float4 nv0 = *(const float4*)&Ns[kk][ty * 8];
            float4 nv1 = *(const float4*)&Ns[kk][ty * 8 + 4];
            float nr[8] = {nv0.x, nv0.y, nv0.z, nv0.w, nv1.x, nv1.y, nv1.z, nv1.w};
            float wr[8];
            #pragma unroll
            for (int i = 0; i < 8; ++i) wr[i] = Wc[kk][tx * 8 + i];
            #pragma unroll
            for (int j = 0; j < 8; ++j)
                #pragma unroll
                for (int i = 0; i < 8; ++i) a[j][i] += nr[j] * wr[i];
        }
    }

    float bb[8];
    #pragma unroll
    for (int i = 0; i < 8; ++i) {
        int o = oz + tx * 8 + i;
        bb[i] = which ? (__ldg(&b1[o]) + __ldg(&b2[o])) : 0.f;
    }
    float* dst = which ? g_baset : g_p1t;
    #pragma unroll
    for (int j = 0; j < 8; ++j) {
        int n = n0 + ty * 8 + j;
        int base = (b * Ndim + n) * Odim + oz + tx * 8;
        float4 v0 = {a[j][0] + bb[0], a[j][1] + bb[1], a[j][2] + bb[2], a[j][3] + bb[3]};
        float4 v1 = {a[j][4] + bb[4], a[j][5] + bb[5], a[j][6] + bb[6], a[j][7] + bb[7]};
        *(float4*)&dst[base]     = v0;
        *(float4*)&dst[base + 4] = v1;
    }
}

// ==============================================================================
// Kernel E: y[b,o,n] = relu(max_k (base[b,n,o] + p1t[b,idx[n,k],o]))
// ==============================================================================
__global__ __launch_bounds__(256) void k_edge(float* __restrict__ out) {
    __shared__ int   idxs[32][16];
    __shared__ float ys[32][257];

    const int b  = blockIdx.y;
    const int n0 = blockIdx.x * 32;
    const int tid = threadIdx.x;

    #pragma unroll
    for (int i = 0; i < 2; ++i) {
        int j = tid + i * 256;
        idxs[j >> 4][j & 15] = g_idx[(b * Ndim + n0 + (j >> 4)) * KNN + (j & 15)];
    }
    __syncthreads();

    #pragma unroll 1
    for (int nn = 0; nn < 32; ++nn) {
        float v = g_baset[(b * Ndim + n0 + nn) * Odim + tid];
        float acc = -FLT_MAX;
        #pragma unroll
        for (int t = 0; t < 16; ++t) {
            int m = idxs[nn][t];
            acc = fmaxf(acc, v + g_p1t[(b * Ndim + m) * Odim + tid]);
        }
        ys[nn][tid] = fmaxf(acc, 0.f);
    }
    __syncthreads();

    #pragma unroll
    for (int i = 0; i < 32; ++i) {
        int j = tid + i * 256;
        int o = j >> 5, n = j & 31;
        out[(b * Odim + o) * Ndim + n0 + n] = ys[n][o];
    }
}

// ==============================================================================
extern "C" void kernel_launch(void* const* d_in, const int* in_sizes, int n_in,
                              void* d_out, int out_size) {
    const float *x = 0, *w0 = 0, *b0 = 0, *w1 = 0, *b1 = 0, *w2 = 0, *b2 = 0;
    for (int i = 0; i < n_in; ++i) {
        const float* p = (const float*)d_in[i];
        switch (in_sizes[i]) {
            case 4194304: x = p; break;
            case 16384:   w0 = p; break;
            case 128:     b0 = p; break;
            case 32768:   if (!w1) w1 = p; else w2 = p; break;
            case 256:     if (!b1) b1 = p; else b2 = p; break;
            default: break; // k, scale scalars
        }
    }
    float* out = (float*)d_out;

    cudaFuncSetAttribute(k_knn, cudaFuncAttributeMaxDynamicSharedMemorySize, SM_TOT);

    k_net  <<<dim3(32, 8),        256>>>(x, w0, b0);
    k_split<<<dim3(128, 4, 8),    256>>>();
    k_knn  <<<dim3(32, 8),        256, SM_TOT>>>();
    k_resc <<<dim3(Ndim / 8, 8),  256>>>();
    k_proj <<<dim3(32, 8, 4),     256>>>(w1, b1, w2, b2);
    k_edge <<<dim3(128, 8),       256>>>(out);
}

// round 10
// speedup vs baseline: 1.0320x; 1.0320x over previous
#include <cuda_runtime.h>
#include <cuda_fp16.h>
#include <float.h>
#include <stdint.h>

#define Bsz  8
#define Cdim 128
#define Ndim 4096
#define Odim 256
#define KNN  16
#define NCAND 40
#define FULLM 0xFFFFFFFFu

// ---------------- scratch (static device globals; no allocations) -------------
__device__ float g_net[Bsz * Cdim * Ndim];     // [b][c][n]      16 MB
__device__ float g_sq[Bsz * Ndim];             // [b][n]
__device__ int   g_idx[Bsz * Ndim * KNN];      // [b][n][k]       2 MB
__device__ float g_p1t[Bsz * Ndim * Odim];     // [b][n][o]      32 MB
__device__ float g_baset[Bsz * Ndim * Odim];   // [b][n][o]      32 MB
__device__ __half g_hi[Bsz * Ndim * Cdim];     // [b][n][c]       8 MB
__device__ float g_netT[Bsz * Ndim * Cdim];    // [b][n][c]      16 MB
__device__ int   g_cand[Bsz * Ndim * NCAND];   // coarse candidate indices

__device__ __forceinline__ uint32_t smem_u32(const void* p) {
    uint32_t a;
    asm("{ .reg .u64 t; cvta.to.shared.u64 t, %1; cvt.u32.u64 %0, t; }" : "=r"(a) : "l"(p));
    return a;
}
__device__ __forceinline__ void ldmx4(uint32_t* r, uint32_t addr) {
    asm volatile("ldmatrix.sync.aligned.m8n8.x4.shared.b16 {%0,%1,%2,%3}, [%4];"
        : "=r"(r[0]), "=r"(r[1]), "=r"(r[2]), "=r"(r[3]) : "r"(addr));
}
__device__ __forceinline__ void mma16816(float* c, const uint32_t* a,
                                         uint32_t b0, uint32_t b1) {
    asm volatile("mma.sync.aligned.m16n8k16.row.col.f32.f16.f16.f32 "
        "{%0,%1,%2,%3}, {%4,%5,%6,%7}, {%8,%9}, {%0,%1,%2,%3};"
        : "+f"(c[0]), "+f"(c[1]), "+f"(c[2]), "+f"(c[3])
        : "r"(a[0]), "r"(a[1]), "r"(a[2]), "r"(a[3]), "r"(b0), "r"(b1));
}

// ==============================================================================
// Kernel A: net = relu(w0 @ x + b0), fused sq[b][n] = sum_c net^2
// ==============================================================================
__global__ __launch_bounds__(256) void k_net(const float* __restrict__ x,
                                             const float* __restrict__ w0,
                                             const float* __restrict__ b0) {
    __shared__ float Ws[32][129];
    __shared__ float Ns[32][128];
    __shared__ float sqs[16][129];

    const int b  = blockIdx.y;
    const int n0 = blockIdx.x * 128;
    const int tid = threadIdx.x;
    const int tx = tid & 15;
    const int ty = tid >> 4;

    float acc[8][8];
    #pragma unroll
    for (int i = 0; i < 8; ++i)
        #pragma unroll
        for (int j = 0; j < 8; ++j) acc[i][j] = 0.f;

    for (int k0 = 0; k0 < 128; k0 += 32) {
        __syncthreads();
        #pragma unroll
        for (int i = 0; i < 16; ++i) {
            int idx = tid + i * 256;
            int cc = idx & 31, o = idx >> 5;
            Ws[cc][o] = w0[o * 128 + k0 + cc];
        }
        #pragma unroll
        for (int i = 0; i < 16; ++i) {
            int idx = tid + i * 256;
            int c = idx >> 7, n = idx & 127;
            Ns[c][n] = x[(b * 128 + k0 + c) * Ndim + n0 + n];
        }
        __syncthreads();
        #pragma unroll
        for (int kk = 0; kk < 32; ++kk) {
            float4 x0 = *(const float4*)&Ns[kk][tx * 8];
            float4 x1 = *(const float4*)&Ns[kk][tx * 8 + 4];
            float xr[8] = {x0.x, x0.y, x0.z, x0.w, x1.x, x1.y, x1.z, x1.w};
            #pragma unroll
            for (int i = 0; i < 8; ++i) {
                float wv = Ws[kk][ty * 8 + i];
                #pragma unroll
                for (int j = 0; j < 8; ++j) acc[i][j] += wv * xr[j];
            }
        }
    }

    float part[8];
    #pragma unroll
    for (int j = 0; j < 8; ++j) part[j] = 0.f;

    #pragma unroll
    for (int i = 0; i < 8; ++i) {
        int o = ty * 8 + i;
        float bv = __ldg(&b0[o]);
        float r[8];
        #pragma unroll
        for (int j = 0; j < 8; ++j) {
            r[j] = fmaxf(acc[i][j] + bv, 0.f);
            part[j] += r[j] * r[j];
        }
        int base = (b * 128 + o) * Ndim + n0 + tx * 8;
        float4 s0 = {r[0], r[1], r[2], r[3]};
        float4 s1 = {r[4], r[5], r[6], r[7]};
        *(float4*)&g_net[base]     = s0;
        *(float4*)&g_net[base + 4] = s1;
    }
    #pragma unroll
    for (int j = 0; j < 8; ++j) sqs[ty][tx * 8 + j] = part[j];
    __syncthreads();
    if (tid < 128) {
        float s = 0.f;
        #pragma unroll
        for (int r = 0; r < 16; ++r) s += sqs[r][tid];
        g_sq[b * Ndim + n0 + tid] = s;
    }
}

// ==============================================================================
// Kernel B: transpose: g_net[b][c][n] -> g_hi (fp16) and g_netT (fp32), [b][n][c]
// ==============================================================================
__global__ __launch_bounds__(256) void k_split() {
    __shared__ float s[32][33];
    const int b  = blockIdx.z;
    const int c0 = blockIdx.y * 32;
    const int n0 = blockIdx.x * 32;
    const int tx = threadIdx.x & 31;
    const int ty = threadIdx.x >> 5;    // 0..7

    #pragma unroll
    for (int i = 0; i < 4; ++i) {
        int c = ty + i * 8;
        s[c][tx] = g_net[(b * Cdim + c0 + c) * Ndim + n0 + tx];
    }
    __syncthreads();
    #pragma unroll
    for (int i = 0; i < 4; ++i) {
        int nl = ty + i * 8;
        float v = s[tx][nl];
        int dst = (b * Ndim + n0 + nl) * Cdim + c0 + tx;
        g_hi[dst]   = __float2half(v);
        g_netT[dst] = v;
    }
}

// ==============================================================================
// Kernel C v9: coarse kNN. 1-pass fp16 gram, R6-verified keys tile + per-query
// (threads 0..127) branchless register top-40 -> g_cand indices.
// grid (32, 8), 256 threads (8 warps). M-tile = 128.
// ==============================================================================
#define PITCHB 272                     // 136 halves/row: conflict-free ldmatrix
#define TILEB  (128 * PITCHB)          // 34816 B per 128x128 fp16 tile
#define SM_QHI 0
#define SM_MHI TILEB
#define SM_KEY (2 * TILEB)             // 128 x 132 floats = 67584 B
#define SM_SQM (SM_KEY + 128 * 132 * 4)
#define SM_TOT (SM_SQM + 512)

__device__ __forceinline__ void load_tile16(char* smem, uint32_t dst,
                                            const __half* __restrict__ src) {
    for (int i = threadIdx.x; i < 2048; i += 256) {
        int row = i >> 4, c8 = (i & 15) * 8;
        uint4 v = *(const uint4*)(src + row * Cdim + c8);
        *(uint4*)(smem + dst + row * PITCHB + c8 * 2) = v;
    }
}

// Branchless sorted insert (registers, static indices). Caller: d < kd[39].
__device__ __forceinline__ void ins40(float (&kd)[NCAND], int (&ki)[NCAND],
                                      float d, int m) {
    int r = 0;
    #pragma unroll
    for (int i = 0; i < NCAND; ++i) r += (kd[i] <= d) ? 1 : 0;
    #pragma unroll
    for (int j = NCAND - 1; j > 0; --j) {
        bool sh = (j > r);
        kd[j] = sh ? kd[j - 1] : kd[j];
        ki[j] = sh ? ki[j - 1] : ki[j];
    }
    #pragma unroll
    for (int j = 0; j < NCAND; ++j)
        if (j == r) { kd[j] = d; ki[j] = m; }
}

__global__ __launch_bounds__(256, 1) void k_knn() {
    extern __shared__ char smem[];
    const uint32_t sbase = smem_u32(smem);
    const int tid  = threadIdx.x;
    const int lane = tid & 31;
    const int wid  = tid >> 5;          // 0..7
    const int b    = blockIdx.y;
    const int n0   = blockIdx.x * 128;
    const int qbase = wid * 16;

    // Stage Q hi tile (128 x 128 fp16) once
    load_tile16(smem, SM_QHI, g_hi + (size_t)(b * Ndim + n0) * Cdim);

    const uint32_t a_base = sbase + SM_QHI + (qbase + (lane & 15)) * PITCHB + ((lane >> 4) << 4);
    const uint32_t b_base = sbase + SM_MHI + ((lane & 7) + ((lane >> 4) << 3)) * PITCHB
                                  + (((lane >> 3) & 1) << 4);

    float* keysp = (float*)(smem + SM_KEY);
    const float* sqm = (const float*)(smem + SM_SQM);

    float kd[NCAND]; int ki[NCAND];
    #pragma unroll
    for (int i = 0; i < NCAND; ++i) { kd[i] = FLT_MAX; ki[i] = 0; }

    for (int mt = 0; mt < 32; ++mt) {
        const int m0 = mt * 128;
        __syncthreads();   // previous scan done; M tile + keys reusable
        load_tile16(smem, SM_MHI, g_hi + (size_t)(b * Ndim + m0) * Cdim);
        if (tid < 128) ((float*)(smem + SM_SQM))[tid] = g_sq[b * Ndim + m0 + tid];
        __syncthreads();

        float c[16][4];
        #pragma unroll
        for (int t = 0; t < 16; ++t)
            #pragma unroll
            for (int e = 0; e < 4; ++e) c[t][e] = 0.f;

        #pragma unroll
        for (int ks = 0; ks < 8; ++ks) {
            uint32_t ra[4];
            ldmx4(ra, a_base + ks * 32);
            #pragma unroll
            for (int tp = 0; tp < 8; ++tp) {
                uint32_t rb[4];
                ldmx4(rb, b_base + tp * (16 * PITCHB) + ks * 32);
                mma16816(c[2 * tp],     ra, rb[0], rb[1]);
                mma16816(c[2 * tp + 1], ra, rb[2], rb[3]);
            }
        }

        // keys[q][m] = sq[m] - 2*dot  (unpacked, R6-verified layout)
        const int q0 = qbase + (lane >> 2);
        const int mo = (lane & 3) * 2;
        #pragma unroll
        for (int t = 0; t < 16; ++t) {
            int m = t * 8 + mo;
            float s0 = sqm[m], s1 = sqm[m + 1];
            *(float2*)&keysp[q0 * 132 + m] =
                make_float2(s0 - 2.f * c[t][0], s1 - 2.f * c[t][1]);
            *(float2*)&keysp[(q0 + 8) * 132 + m] =
                make_float2(s0 - 2.f * c[t][2], s1 - 2.f * c[t][3]);
        }
        __syncthreads();

        // coarse scan: threads 0..127, one query each (R6-verified structure)
        if (tid < 128) {
            const float* krow = keysp + tid * 132;
            #pragma unroll 4
            for (int m = 0; m < 128; ++m) {
                float kv = krow[m];
                if (kv < kd[NCAND - 1]) ins40(kd, ki, kv, m0 + m);
            }
        }
    }

    if (tid < 128) {
        int* crow = g_cand + ((size_t)(b * Ndim + n0 + tid)) * NCAND;
        #pragma unroll
        for (int i = 0; i < NCAND; ++i) crow[i] = ki[i];
    }
}

// ==============================================================================
// Kernel C2: exact fp32 rescore of 40 candidates/query + exact top-17 extract.
// grid (Ndim/8, Bsz), 256 threads: warp w handles query blockIdx.x*8 + w.
// Entries 32..39 are 4x lane-duplicated; dups are killed jointly.
// ==============================================================================
__global__ __launch_bounds__(256) void k_resc() {
    const int lane = threadIdx.x & 31;
    const int wid  = threadIdx.x >> 5;
    const int b    = blockIdx.y;
    const int q    = blockIdx.x * 8 + wid;

    const float4 qv = *(const float4*)&g_netT[(size_t)(b * Ndim + q) * Cdim + lane * 4];
    const int* crow = g_cand + ((size_t)(b * Ndim + q)) * NCAND;
    int ma = crow[lane];                // entries 0..31
    int mb = crow[32 + (lane & 7)];     // entries 32..39 (4x dup)

    float part[NCAND];
    #pragma unroll
    for (int ci = 0; ci < NCAND; ++ci) {
        int m = __shfl_sync(FULLM, (ci < 32) ? ma : mb, (ci < 32) ? ci : (ci - 32));
        float4 mv = *(const float4*)&g_netT[(size_t)(b * Ndim + m) * Cdim + lane * 4];
        part[ci] = qv.x * mv.x + qv.y * mv.y + qv.z * mv.z + qv.w * mv.w;
    }
    #pragma unroll
    for (int ci = 0; ci < NCAND; ++ci) {
        float v = part[ci];
        v += __shfl_xor_sync(FULLM, v, 16);
        v += __shfl_xor_sync(FULLM, v, 8);
        v += __shfl_xor_sync(FULLM, v, 4);
        v += __shfl_xor_sync(FULLM, v, 2);
        v += __shfl_xor_sync(FULLM, v, 1);
        part[ci] = v;
    }
    float da = 0.f, db = 0.f;
    #pragma unroll
    for (int ci = 0; ci < 32; ++ci) da = (ci == lane) ? part[ci] : da;
    #pragma unroll
    for (int ci = 32; ci < NCAND; ++ci) db = ((ci - 32) == (lane & 7)) ? part[ci] : db;

    float ka = __ldg(&g_sq[b * Ndim + ma]) - 2.f * da;
    float kb = __ldg(&g_sq[b * Ndim + mb]) - 2.f * db;

    int* orow = g_idx + ((size_t)(b * Ndim + q)) * KNN;
    #pragma unroll 1
    for (int t = 0; t < 17; ++t) {
        bool sa = (ka < kb) || (ka == kb && ma < mb);
        float lk = sa ? ka : kb;
        int   lm = sa ? ma : mb;
        #pragma unroll
        for (int d = 16; d > 0; d >>= 1) {
            float ok = __shfl_xor_sync(FULLM, lk, d);
            int   om = __shfl_xor_sync(FULLM, lm, d);
            bool take = (ok < lk) || (ok == lk && om < lm);
            lk = take ? ok : lk;
            lm = take ? om : lm;
        }
        if (t > 0 && lane == 0) orow[t - 1] = lm;   // t=0 = self (strict min) dropped
        if (ma == lm) ka = FLT_MAX;
        if (mb == lm) kb = FLT_MAX;
    }
}

// ==============================================================================
// Kernel D: two independent 64-reg GEMMs selected by z&1:
//   which=0: p1   = w1@net                  -> g_p1t  [b][n][o]
//   which=1: base = (w2-w1)@net + (b1+b2)   -> g_baset[b][n][o]
// ==============================================================================
__global__ __launch_bounds__(256) void k_proj(const float* __restrict__ w1,
                                              const float* __restrict__ b1,
                                              const float* __restrict__ w2,
                                              const float* __restrict__ b2) {
    __shared__ float Wc[16][129];   // [c-chunk][o]
    __shared__ float Ns[16][128];   // [c-chunk][n]

    const int b     = blockIdx.y;
    const int n0    = blockIdx.x * 128;
    const int which = blockIdx.z & 1;
    const int oz    = (blockIdx.z >> 1) * 128;
    const int tid = threadIdx.x;
    const int tx = tid & 15;        // o group
    const int ty = tid >> 4;        // n group

    float a[8][8];
    #pragma unroll
    for (int j = 0; j < 8; ++j)
        #pragma unroll
        for (int i = 0; i < 8; ++i) a[j][i] = 0.f;

    for (int k0 = 0; k0 < 128; k0 += 16) {
        __syncthreads();
        #pragma unroll
        for (int i = 0; i < 8; ++i) {
            int idx = tid + i * 256;
            int cc = idx & 15, o = idx >> 4;
            float wv = w1[(oz + o) * 128 + k0 + cc];
            if (which) wv = w2[(oz + o) * 128 + k0 + cc] - wv;
            Wc[cc][o] = wv;
        }
        #pragma unroll
        for (int i = 0; i < 8; ++i) {
            int idx = tid + i * 256;
            int c = idx >> 7, n = idx & 127;
            Ns[c][n] = g_net[(b * 128 + k0 + c) * Ndim + n0 + n];
        }
        __syncthreads();
        #pragma unroll
        for (int kk = 0; kk < 16; ++kk) {
            float4 nv0 = *(const float4*)&Ns[kk][ty * 8];
            float4 nv1 = *(const float4*)&Ns[kk][ty * 8 + 4];
            float nr[8] = {nv0.x, nv0.y, nv0.z, nv0.w, nv1.x, nv1.y, nv1.z, nv1.w};
            float wr[8];
            #pragma unroll
            for (int i = 0; i < 8; ++i) wr[i] = Wc[kk][tx * 8 + i];
            #pragma unroll
            for (int j = 0; j < 8; ++j)
                #pragma unroll
                for (int i = 0; i < 8; ++i) a[j][i] += nr[j] * wr[i];
        }
    }

    float bb[8];
    #pragma unroll
    for (int i = 0; i < 8; ++i) {
        int o = oz + tx * 8 + i;
        bb[i] = which ? (__ldg(&b1[o]) + __ldg(&b2[o])) : 0.f;
    }
    float* dst = which ? g_baset : g_p1t;
    #pragma unroll
    for (int j = 0; j < 8; ++j) {
        int n = n0 + ty * 8 + j;
        int base = (b * Ndim + n) * Odim + oz + tx * 8;
        float4 v0 = {a[j][0] + bb[0], a[j][1] + bb[1], a[j][2] + bb[2], a[j][3] + bb[3]};
        float4 v1 = {a[j][4] + bb[4], a[j][5] + bb[5], a[j][6] + bb[6], a[j][7] + bb[7]};
        *(float4*)&dst[base]     = v0;
        *(float4*)&dst[base + 4] = v1;
    }
}

// ==============================================================================
// Kernel E: y[b,o,n] = relu(max_k (base[b,n,o] + p1t[b,idx[n,k],o]))
// ==============================================================================
__global__ __launch_bounds__(256) void k_edge(float* __restrict__ out) {
    __shared__ int   idxs[32][16];
    __shared__ float ys[32][257];

    const int b  = blockIdx.y;
    const int n0 = blockIdx.x * 32;
    const int tid = threadIdx.x;

    #pragma unroll
    for (int i = 0; i < 2; ++i) {
        int j = tid + i * 256;
        idxs[j >> 4][j & 15] = g_idx[(b * Ndim + n0 + (j >> 4)) * KNN + (j & 15)];
    }
    __syncthreads();

    #pragma unroll 1
    for (int nn = 0; nn < 32; ++nn) {
        float v = g_baset[(b * Ndim + n0 + nn) * Odim + tid];
        float acc = -FLT_MAX;
        #pragma unroll
        for (int t = 0; t < 16; ++t) {
            int m = idxs[nn][t];
            acc = fmaxf(acc, v + g_p1t[(b * Ndim + m) * Odim + tid]);
        }
        ys[nn][tid] = fmaxf(acc, 0.f);
    }
    __syncthreads();

    #pragma unroll
    for (int i = 0; i < 32; ++i) {
        int j = tid + i * 256;
        int o = j >> 5, n = j & 31;
        out[(b * Odim + o) * Ndim + n0 + n] = ys[n][o];
    }
}

// ==============================================================================
extern "C" void kernel_launch(void* const* d_in, const int* in_sizes, int n_in,
                              void* d_out, int out_size) {
    const float *x = 0, *w0 = 0, *b0 = 0, *w1 = 0, *b1 = 0, *w2 = 0, *b2 = 0;
    for (int i = 0; i < n_in; ++i) {
        const float* p = (const float*)d_in[i];
        switch (in_sizes[i]) {
            case 4194304: x = p; break;
            case 16384:   w0 = p; break;
            case 128:     b0 = p; break;
            case 32768:   if (!w1) w1 = p; else w2 = p; break;
            case 256:     if (!b1) b1 = p; else b2 = p; break;
            default: break; // k, scale scalars
        }
    }
    float* out = (float*)d_out;

    cudaFuncSetAttribute(k_knn, cudaFuncAttributeMaxDynamicSharedMemorySize, SM_TOT);

    k_net  <<<dim3(32, 8),        256>>>(x, w0, b0);
    k_split<<<dim3(128, 4, 8),    256>>>();
    k_knn  <<<dim3(32, 8),        256, SM_TOT>>>();
    k_resc <<<dim3(Ndim / 8, 8),  256>>>();
    k_proj <<<dim3(32, 8, 4),     256>>>(w1, b1, w2, b2);
    k_edge <<<dim3(128, 8),       256>>>(out);
}

// round 11
// speedup vs baseline: 5.0365x; 4.8804x over previous
#include <cuda_runtime.h>
#include <cuda_fp16.h>
#include <float.h>
#include <stdint.h>

#define Bsz  8
#define Cdim 128
#define Ndim 4096
#define Odim 256
#define KNN  16
#define NCAND 24
#define FULLM 0xFFFFFFFFu

// ---------------- scratch (static device globals; no allocations) -------------
__device__ float g_net[Bsz * Cdim * Ndim];     // [b][c][n]      16 MB
__device__ float g_sq[Bsz * Ndim];             // [b][n]
__device__ int   g_idx[Bsz * Ndim * KNN];      // [b][n][k]       2 MB
__device__ float g_p1t[Bsz * Ndim * Odim];     // [b][n][o]      32 MB
__device__ float g_baset[Bsz * Ndim * Odim];   // [b][n][o]      32 MB
__device__ __half g_hi[Bsz * Ndim * Cdim];     // [b][n][c]       8 MB
__device__ float g_netT[Bsz * Ndim * Cdim];    // [b][n][c]      16 MB
__device__ int   g_cand[Bsz * Ndim * NCAND];   // coarse candidate indices

__device__ __forceinline__ uint32_t smem_u32(const void* p) {
    uint32_t a;
    asm("{ .reg .u64 t; cvta.to.shared.u64 t, %1; cvt.u32.u64 %0, t; }" : "=r"(a) : "l"(p));
    return a;
}
__device__ __forceinline__ void ldmx4(uint32_t* r, uint32_t addr) {
    asm volatile("ldmatrix.sync.aligned.m8n8.x4.shared.b16 {%0,%1,%2,%3}, [%4];"
        : "=r"(r[0]), "=r"(r[1]), "=r"(r[2]), "=r"(r[3]) : "r"(addr));
}
__device__ __forceinline__ void mma16816(float* c, const uint32_t* a,
                                         uint32_t b0, uint32_t b1) {
    asm volatile("mma.sync.aligned.m16n8k16.row.col.f32.f16.f16.f32 "
        "{%0,%1,%2,%3}, {%4,%5,%6,%7}, {%8,%9}, {%0,%1,%2,%3};"
        : "+f"(c[0]), "+f"(c[1]), "+f"(c[2]), "+f"(c[3])
        : "r"(a[0]), "r"(a[1]), "r"(a[2]), "r"(a[3]), "r"(b0), "r"(b1));
}

// ==============================================================================
// Kernel A: net = relu(w0 @ x + b0), fused sq[b][n] = sum_c net^2
// ==============================================================================
__global__ __launch_bounds__(256) void k_net(const float* __restrict__ x,
                                             const float* __restrict__ w0,
                                             const float* __restrict__ b0) {
    __shared__ float Ws[32][129];
    __shared__ float Ns[32][128];
    __shared__ float sqs[16][129];

    const int b  = blockIdx.y;
    const int n0 = blockIdx.x * 128;
    const int tid = threadIdx.x;
    const int tx = tid & 15;
    const int ty = tid >> 4;

    float acc[8][8];
    #pragma unroll
    for (int i = 0; i < 8; ++i)
        #pragma unroll
        for (int j = 0; j < 8; ++j) acc[i][j] = 0.f;

    for (int k0 = 0; k0 < 128; k0 += 32) {
        __syncthreads();
        #pragma unroll
        for (int i = 0; i < 16; ++i) {
            int idx = tid + i * 256;
            int cc = idx & 31, o = idx >> 5;
            Ws[cc][o] = w0[o * 128 + k0 + cc];
        }
        #pragma unroll
        for (int i = 0; i < 16; ++i) {
            int idx = tid + i * 256;
            int c = idx >> 7, n = idx & 127;
            Ns[c][n] = x[(b * 128 + k0 + c) * Ndim + n0 + n];
        }
        __syncthreads();
        #pragma unroll
        for (int kk = 0; kk < 32; ++kk) {
            float4 x0 = *(const float4*)&Ns[kk][tx * 8];
            float4 x1 = *(const float4*)&Ns[kk][tx * 8 + 4];
            float xr[8] = {x0.x, x0.y, x0.z, x0.w, x1.x, x1.y, x1.z, x1.w};
            #pragma unroll
            for (int i = 0; i < 8; ++i) {
                float wv = Ws[kk][ty * 8 + i];
                #pragma unroll
                for (int j = 0; j < 8; ++j) acc[i][j] += wv * xr[j];
            }
        }
    }

    float part[8];
    #pragma unroll
    for (int j = 0; j < 8; ++j) part[j] = 0.f;

    #pragma unroll
    for (int i = 0; i < 8; ++i) {
        int o = ty * 8 + i;
        float bv = __ldg(&b0[o]);
        float r[8];
        #pragma unroll
        for (int j = 0; j < 8; ++j) {
            r[j] = fmaxf(acc[i][j] + bv, 0.f);
            part[j] += r[j] * r[j];
        }
        int base = (b * 128 + o) * Ndim + n0 + tx * 8;
        float4 s0 = {r[0], r[1], r[2], r[3]};
        float4 s1 = {r[4], r[5], r[6], r[7]};
        *(float4*)&g_net[base]     = s0;
        *(float4*)&g_net[base + 4] = s1;
    }
    #pragma unroll
    for (int j = 0; j < 8; ++j) sqs[ty][tx * 8 + j] = part[j];
    __syncthreads();
    if (tid < 128) {
        float s = 0.f;
        #pragma unroll
        for (int r = 0; r < 16; ++r) s += sqs[r][tid];
        g_sq[b * Ndim + n0 + tid] = s;
    }
}

// ==============================================================================
// Kernel B: transpose: g_net[b][c][n] -> g_hi (fp16) and g_netT (fp32), [b][n][c]
// ==============================================================================
__global__ __launch_bounds__(256) void k_split() {
    __shared__ float s[32][33];
    const int b  = blockIdx.z;
    const int c0 = blockIdx.y * 32;
    const int n0 = blockIdx.x * 32;
    const int tx = threadIdx.x & 31;
    const int ty = threadIdx.x >> 5;    // 0..7

    #pragma unroll
    for (int i = 0; i < 4; ++i) {
        int c = ty + i * 8;
        s[c][tx] = g_net[(b * Cdim + c0 + c) * Ndim + n0 + tx];
    }
    __syncthreads();
    #pragma unroll
    for (int i = 0; i < 4; ++i) {
        int nl = ty + i * 8;
        float v = s[tx][nl];
        int dst = (b * Ndim + n0 + nl) * Cdim + c0 + tx;
        g_hi[dst]   = __float2half(v);
        g_netT[dst] = v;
    }
}

// ==============================================================================
// Kernel C v11: coarse kNN. 1-pass fp16 gram, R6-verified keys tile + per-query
// (threads 0..127) branchless register top-24 -> g_cand indices.
// grid (32, 8), 256 threads (8 warps). M-tile = 128.
// ==============================================================================
#define PITCHB 272                     // 136 halves/row: conflict-free ldmatrix
#define TILEB  (128 * PITCHB)          // 34816 B per 128x128 fp16 tile
#define SM_QHI 0
#define SM_MHI TILEB
#define SM_KEY (2 * TILEB)             // 128 x 132 floats = 67584 B
#define SM_SQM (SM_KEY + 128 * 132 * 4)
#define SM_TOT (SM_SQM + 512)

__device__ __forceinline__ void load_tile16(char* smem, uint32_t dst,
                                            const __half* __restrict__ src) {
    for (int i = threadIdx.x; i < 2048; i += 256) {
        int row = i >> 4, c8 = (i & 15) * 8;
        uint4 v = *(const uint4*)(src + row * Cdim + c8);
        *(uint4*)(smem + dst + row * PITCHB + c8 * 2) = v;
    }
}

// Branchless sorted insert (registers, static indices). Caller: d < kd[NCAND-1].
__device__ __forceinline__ void ins24(float (&kd)[NCAND], int (&ki)[NCAND],
                                      float d, int m) {
    int r = 0;
    #pragma unroll
    for (int i = 0; i < NCAND; ++i) r += (kd[i] <= d) ? 1 : 0;
    #pragma unroll
    for (int j = NCAND - 1; j > 0; --j) {
        bool sh = (j > r);
        kd[j] = sh ? kd[j - 1] : kd[j];
        ki[j] = sh ? ki[j - 1] : ki[j];
    }
    #pragma unroll
    for (int j = 0; j < NCAND; ++j)
        if (j == r) { kd[j] = d; ki[j] = m; }
}

__global__ __launch_bounds__(256, 1) void k_knn() {
    extern __shared__ char smem[];
    const uint32_t sbase = smem_u32(smem);
    const int tid  = threadIdx.x;
    const int lane = tid & 31;
    const int wid  = tid >> 5;          // 0..7
    const int b    = blockIdx.y;
    const int n0   = blockIdx.x * 128;
    const int qbase = wid * 16;

    // Stage Q hi tile (128 x 128 fp16) once
    load_tile16(smem, SM_QHI, g_hi + (size_t)(b * Ndim + n0) * Cdim);

    const uint32_t a_base = sbase + SM_QHI + (qbase + (lane & 15)) * PITCHB + ((lane >> 4) << 4);
    const uint32_t b_base = sbase + SM_MHI + ((lane & 7) + ((lane >> 4) << 3)) * PITCHB
                                  + (((lane >> 3) & 1) << 4);

    float* keysp = (float*)(smem + SM_KEY);
    const float* sqm = (const float*)(smem + SM_SQM);

    float kd[NCAND]; int ki[NCAND];
    #pragma unroll
    for (int i = 0; i < NCAND; ++i) { kd[i] = FLT_MAX; ki[i] = 0; }

    for (int mt = 0; mt < 32; ++mt) {
        const int m0 = mt * 128;
        __syncthreads();   // previous scan done; M tile + keys reusable
        load_tile16(smem, SM_MHI, g_hi + (size_t)(b * Ndim + m0) * Cdim);
        if (tid < 128) ((float*)(smem + SM_SQM))[tid] = g_sq[b * Ndim + m0 + tid];
        __syncthreads();

        float c[16][4];
        #pragma unroll
        for (int t = 0; t < 16; ++t)
            #pragma unroll
            for (int e = 0; e < 4; ++e) c[t][e] = 0.f;

        #pragma unroll
        for (int ks = 0; ks < 8; ++ks) {
            uint32_t ra[4];
            ldmx4(ra, a_base + ks * 32);
            #pragma unroll
            for (int tp = 0; tp < 8; ++tp) {
                uint32_t rb[4];
                ldmx4(rb, b_base + tp * (16 * PITCHB) + ks * 32);
                mma16816(c[2 * tp],     ra, rb[0], rb[1]);
                mma16816(c[2 * tp + 1], ra, rb[2], rb[3]);
            }
        }

        // keys[q][m] = sq[m] - 2*dot  (unpacked, R6-verified layout)
        const int q0 = qbase + (lane >> 2);
        const int mo = (lane & 3) * 2;
        #pragma unroll
        for (int t = 0; t < 16; ++t) {
            int m = t * 8 + mo;
            float s0 = sqm[m], s1 = sqm[m + 1];
            *(float2*)&keysp[q0 * 132 + m] =
                make_float2(s0 - 2.f * c[t][0], s1 - 2.f * c[t][1]);
            *(float2*)&keysp[(q0 + 8) * 132 + m] =
                make_float2(s0 - 2.f * c[t][2], s1 - 2.f * c[t][3]);
        }
        __syncthreads();

        // coarse scan: threads 0..127, one query each (R6-verified structure)
        if (tid < 128) {
            const float* krow = keysp + tid * 132;
            #pragma unroll 4
            for (int m = 0; m < 128; ++m) {
                float kv = krow[m];
                if (kv < kd[NCAND - 1]) ins24(kd, ki, kv, m0 + m);
            }
        }
    }

    if (tid < 128) {
        int* crow = g_cand + ((size_t)(b * Ndim + n0 + tid)) * NCAND;
        #pragma unroll
        for (int i = 0; i < NCAND; ++i) crow[i] = ki[i];
    }
}

// ==============================================================================
// Kernel C2: exact fp32 rescore of 24 candidates/query + exact top-17 extract.
// grid (Ndim/8, Bsz), 256 threads: warp w handles query blockIdx.x*8 + w.
// Lanes 24..31 duplicate entries 16..23; duplicates are killed jointly.
// ==============================================================================
__global__ __launch_bounds__(256) void k_resc() {
    const int lane = threadIdx.x & 31;
    const int wid  = threadIdx.x >> 5;
    const int b    = blockIdx.y;
    const int q    = blockIdx.x * 8 + wid;

    const float4 qv = *(const float4*)&g_netT[(size_t)(b * Ndim + q) * Cdim + lane * 4];
    const int* crow = g_cand + ((size_t)(b * Ndim + q)) * NCAND;
    const int myent = (lane < NCAND) ? lane : (lane - 8);   // entries; 24..31 dup 16..23
    int ma = crow[myent];

    float part[NCAND];
    #pragma unroll
    for (int ci = 0; ci < NCAND; ++ci) {
        int m = __shfl_sync(FULLM, ma, ci);
        float4 mv = *(const float4*)&g_netT[(size_t)(b * Ndim + m) * Cdim + lane * 4];
        part[ci] = qv.x * mv.x + qv.y * mv.y + qv.z * mv.z + qv.w * mv.w;
    }
    #pragma unroll
    for (int ci = 0; ci < NCAND; ++ci) {
        float v = part[ci];
        v += __shfl_xor_sync(FULLM, v, 16);
        v += __shfl_xor_sync(FULLM, v, 8);
        v += __shfl_xor_sync(FULLM, v, 4);
        v += __shfl_xor_sync(FULLM, v, 2);
        v += __shfl_xor_sync(FULLM, v, 1);
        part[ci] = v;
    }
    float da = 0.f;
    #pragma unroll
    for (int ci = 0; ci < NCAND; ++ci) da = (myent == ci) ? part[ci] : da;

    float ka = __ldg(&g_sq[b * Ndim + ma]) - 2.f * da;

    int* orow = g_idx + ((size_t)(b * Ndim + q)) * KNN;
    #pragma unroll 1
    for (int t = 0; t < 17; ++t) {
        float lk = ka;
        int   lm = ma;
        #pragma unroll
        for (int d = 16; d > 0; d >>= 1) {
            float ok = __shfl_xor_sync(FULLM, lk, d);
            int   om = __shfl_xor_sync(FULLM, lm, d);
            bool take = (ok < lk) || (ok == lk && om < lm);
            lk = take ? ok : lk;
            lm = take ? om : lm;
        }
        if (t > 0 && lane == 0) orow[t - 1] = lm;   // t=0 = self (strict min) dropped
        if (ma == lm) ka = FLT_MAX;                  // kills duplicates jointly
    }
}

// ==============================================================================
// Kernel D: two independent 64-reg GEMMs selected by z&1:
//   which=0: p1   = w1@net                  -> g_p1t  [b][n][o]
//   which=1: base = (w2-w1)@net + (b1+b2)   -> g_baset[b][n][o]
// ==============================================================================
__global__ __launch_bounds__(256) void k_proj(const float* __restrict__ w1,
                                              const float* __restrict__ b1,
                                              const float* __restrict__ w2,
                                              const float* __restrict__ b2) {
    __shared__ float Wc[16][129];   // [c-chunk][o]
    __shared__ float Ns[16][128];   // [c-chunk][n]

    const int b     = blockIdx.y;
    const int n0    = blockIdx.x * 128;
    const int which = blockIdx.z & 1;
    const int oz    = (blockIdx.z >> 1) * 128;
    const int tid = threadIdx.x;
    const int tx = tid & 15;        // o group
    const int ty = tid >> 4;        // n group

    float a[8][8];
    #pragma unroll
    for (int j = 0; j < 8; ++j)
        #pragma unroll
        for (int i = 0; i < 8; ++i) a[j][i] = 0.f;

    for (int k0 = 0; k0 < 128; k0 += 16) {
        __syncthreads();
        #pragma unroll
        for (int i = 0; i < 8; ++i) {
            int idx = tid + i * 256;
            int cc = idx & 15, o = idx >> 4;
            float wv = w1[(oz + o) * 128 + k0 + cc];
            if (which) wv = w2[(oz + o) * 128 + k0 + cc] - wv;
            Wc[cc][o] = wv;
        }
        #pragma unroll
        for (int i = 0; i < 8; ++i) {
            int idx = tid + i * 256;
            int c = idx >> 7, n = idx & 127;
            Ns[c][n] = g_net[(b * 128 + k0 + c) * Ndim + n0 + n];
        }
        __syncthreads();
        #pragma unroll
        for (int kk = 0; kk < 16; ++kk) {
            float4 nv0 = *(const float4*)&Ns[kk][ty * 8];
            float4 nv1 = *(const float4*)&Ns[kk][ty * 8 + 4];
            float nr[8] = {nv0.x, nv0.y, nv0.z, nv0.w, nv1.x, nv1.y, nv1.z, nv1.w};
            float wr[8];
            #pragma unroll
            for (int i = 0; i < 8; ++i) wr[i] = Wc[kk][tx * 8 + i];
            #pragma unroll
            for (int j = 0; j < 8; ++j)
                #pragma unroll
                for (int i = 0; i < 8; ++i) a[j][i] += nr[j] * wr[i];
        }
    }

    float bb[8];
    #pragma unroll
    for (int i = 0; i < 8; ++i) {
        int o = oz + tx * 8 + i;
        bb[i] = which ? (__ldg(&b1[o]) + __ldg(&b2[o])) : 0.f;
    }
    float* dst = which ? g_baset : g_p1t;
    #pragma unroll
    for (int j = 0; j < 8; ++j) {
        int n = n0 + ty * 8 + j;
        int base = (b * Ndim + n) * Odim + oz + tx * 8;
        float4 v0 = {a[j][0] + bb[0], a[j][1] + bb[1], a[j][2] + bb[2], a[j][3] + bb[3]};
        float4 v1 = {a[j][4] + bb[4], a[j][5] + bb[5], a[j][6] + bb[6], a[j][7] + bb[7]};
        *(float4*)&dst[base]     = v0;
        *(float4*)&dst[base + 4] = v1;
    }
}

// ==============================================================================
// Kernel E: y[b,o,n] = relu(max_k (base[b,n,o] + p1t[b,idx[n,k],o]))
// ==============================================================================
__global__ __launch_bounds__(256) void k_edge(float* __restrict__ out) {
    __shared__ int   idxs[32][16];
    __shared__ float ys[32][257];

    const int b  = blockIdx.y;
    const int n0 = blockIdx.x * 32;
    const int tid = threadIdx.x;

    #pragma unroll
    for (int i = 0; i < 2; ++i) {
        int j = tid + i * 256;
        idxs[j >> 4][j & 15] = g_idx[(b * Ndim + n0 + (j >> 4)) * KNN + (j & 15)];
    }
    __syncthreads();

    #pragma unroll 1
    for (int nn = 0; nn < 32; ++nn) {
        float v = g_baset[(b * Ndim + n0 + nn) * Odim + tid];
        float acc = -FLT_MAX;
        #pragma unroll
        for (int t = 0; t < 16; ++t) {
            int m = idxs[nn][t];
            acc = fmaxf(acc, v + g_p1t[(b * Ndim + m) * Odim + tid]);
        }
        ys[nn][tid] = fmaxf(acc, 0.f);
    }
    __syncthreads();

    #pragma unroll
    for (int i = 0; i < 32; ++i) {
        int j = tid + i * 256;
        int o = j >> 5, n = j & 31;
        out[(b * Odim + o) * Ndim + n0 + n] = ys[n][o];
    }
}

// ==============================================================================
extern "C" void kernel_launch(void* const* d_in, const int* in_sizes, int n_in,
                              void* d_out, int out_size) {
    const float *x = 0, *w0 = 0, *b0 = 0, *w1 = 0, *b1 = 0, *w2 = 0, *b2 = 0;
    for (int i = 0; i < n_in; ++i) {
        const float* p = (const float*)d_in[i];
        switch (in_sizes[i]) {
            case 4194304: x = p; break;
            case 16384:   w0 = p; break;
            case 128:     b0 = p; break;
            case 32768:   if (!w1) w1 = p; else w2 = p; break;
            case 256:     if (!b1) b1 = p; else b2 = p; break;
            default: break; // k, scale scalars
        }
    }
    float* out = (float*)d_out;

    cudaFuncSetAttribute(k_knn, cudaFuncAttributeMaxDynamicSharedMemorySize, SM_TOT);

    k_net  <<<dim3(32, 8),        256>>>(x, w0, b0);
    k_split<<<dim3(128, 4, 8),    256>>>();
    k_knn  <<<dim3(32, 8),        256, SM_TOT>>>();
    k_resc <<<dim3(Ndim / 8, 8),  256>>>();
    k_proj <<<dim3(32, 8, 4),     256>>>(w1, b1, w2, b2);
    k_edge <<<dim3(128, 8),       256>>>(out);
}

// round 12
// speedup vs baseline: 21.5888x; 4.2864x over previous
#include <cuda_runtime.h>
#include <cuda_fp16.h>
#include <float.h>
#include <stdint.h>

#define Bsz  8
#define Cdim 128
#define Ndim 4096
#define Odim 256
#define KNN  16
#define NCAND 32
#define FULLM 0xFFFFFFFFu

// ---------------- scratch (static device globals; no allocations) -------------
__device__ float g_net[Bsz * Cdim * Ndim];     // [b][c][n]      16 MB
__device__ float g_sq[Bsz * Ndim];             // [b][n]
__device__ int   g_idx[Bsz * Ndim * KNN];      // [b][n][k]       2 MB
__device__ float g_p1t[Bsz * Ndim * Odim];     // [b][n][o]      32 MB
__device__ float g_baset[Bsz * Ndim * Odim];   // [b][n][o]      32 MB
__device__ __half g_hi[Bsz * Ndim * Cdim];     // [b][n][c]       8 MB
__device__ float g_netT[Bsz * Ndim * Cdim];    // [b][n][c]      16 MB
__device__ int   g_cand[Bsz * Ndim * NCAND];   // coarse candidate indices

__device__ __forceinline__ uint32_t smem_u32(const void* p) {
    uint32_t a;
    asm("{ .reg .u64 t; cvta.to.shared.u64 t, %1; cvt.u32.u64 %0, t; }" : "=r"(a) : "l"(p));
    return a;
}
__device__ __forceinline__ void ldmx4(uint32_t* r, uint32_t addr) {
    asm volatile("ldmatrix.sync.aligned.m8n8.x4.shared.b16 {%0,%1,%2,%3}, [%4];"
        : "=r"(r[0]), "=r"(r[1]), "=r"(r[2]), "=r"(r[3]) : "r"(addr));
}
__device__ __forceinline__ void mma16816(float* c, const uint32_t* a,
                                         uint32_t b0, uint32_t b1) {
    asm volatile("mma.sync.aligned.m16n8k16.row.col.f32.f16.f16.f32 "
        "{%0,%1,%2,%3}, {%4,%5,%6,%7}, {%8,%9}, {%0,%1,%2,%3};"
        : "+f"(c[0]), "+f"(c[1]), "+f"(c[2]), "+f"(c[3])
        : "r"(a[0]), "r"(a[1]), "r"(a[2]), "r"(a[3]), "r"(b0), "r"(b1));
}

// ==============================================================================
// Kernel A: net = relu(w0 @ x + b0), fused sq[b][n] = sum_c net^2
// ==============================================================================
__global__ __launch_bounds__(256) void k_net(const float* __restrict__ x,
                                             const float* __restrict__ w0,
                                             const float* __restrict__ b0) {
    __shared__ float Ws[32][129];
    __shared__ float Ns[32][128];
    __shared__ float sqs[16][129];

    const int b  = blockIdx.y;
    const int n0 = blockIdx.x * 128;
    const int tid = threadIdx.x;
    const int tx = tid & 15;
    const int ty = tid >> 4;

    float acc[8][8];
    #pragma unroll
    for (int i = 0; i < 8; ++i)
        #pragma unroll
        for (int j = 0; j < 8; ++j) acc[i][j] = 0.f;

    for (int k0 = 0; k0 < 128; k0 += 32) {
        __syncthreads();
        #pragma unroll
        for (int i = 0; i < 16; ++i) {
            int idx = tid + i * 256;
            int cc = idx & 31, o = idx >> 5;
            Ws[cc][o] = w0[o * 128 + k0 + cc];
        }
        #pragma unroll
        for (int i = 0; i < 16; ++i) {
            int idx = tid + i * 256;
            int c = idx >> 7, n = idx & 127;
            Ns[c][n] = x[(b * 128 + k0 + c) * Ndim + n0 + n];
        }
        __syncthreads();
        #pragma unroll
        for (int kk = 0; kk < 32; ++kk) {
            float4 x0 = *(const float4*)&Ns[kk][tx * 8];
            float4 x1 = *(const float4*)&Ns[kk][tx * 8 + 4];
            float xr[8] = {x0.x, x0.y, x0.z, x0.w, x1.x, x1.y, x1.z, x1.w};
            #pragma unroll
            for (int i = 0; i < 8; ++i) {
                float wv = Ws[kk][ty * 8 + i];
                #pragma unroll
                for (int j = 0; j < 8; ++j) acc[i][j] += wv * xr[j];
            }
        }
    }

    float part[8];
    #pragma unroll
    for (int j = 0; j < 8; ++j) part[j] = 0.f;

    #pragma unroll
    for (int i = 0; i < 8; ++i) {
        int o = ty * 8 + i;
        float bv = __ldg(&b0[o]);
        float r[8];
        #pragma unroll
        for (int j = 0; j < 8; ++j) {
            r[j] = fmaxf(acc[i][j] + bv, 0.f);
            part[j] += r[j] * r[j];
        }
        int base = (b * 128 + o) * Ndim + n0 + tx * 8;
        float4 s0 = {r[0], r[1], r[2], r[3]};
        float4 s1 = {r[4], r[5], r[6], r[7]};
        *(float4*)&g_net[base]     = s0;
        *(float4*)&g_net[base + 4] = s1;
    }
    #pragma unroll
    for (int j = 0; j < 8; ++j) sqs[ty][tx * 8 + j] = part[j];
    __syncthreads();
    if (tid < 128) {
        float s = 0.f;
        #pragma unroll
        for (int r = 0; r < 16; ++r) s += sqs[r][tid];
        g_sq[b * Ndim + n0 + tid] = s;
    }
}

// ==============================================================================
// Kernel B: transpose: g_net[b][c][n] -> g_hi (fp16) and g_netT (fp32), [b][n][c]
// ==============================================================================
__global__ __launch_bounds__(256) void k_split() {
    __shared__ float s[32][33];
    const int b  = blockIdx.z;
    const int c0 = blockIdx.y * 32;
    const int n0 = blockIdx.x * 32;
    const int tx = threadIdx.x & 31;
    const int ty = threadIdx.x >> 5;    // 0..7

    #pragma unroll
    for (int i = 0; i < 4; ++i) {
        int c = ty + i * 8;
        s[c][tx] = g_net[(b * Cdim + c0 + c) * Ndim + n0 + tx];
    }
    __syncthreads();
    #pragma unroll
    for (int i = 0; i < 4; ++i) {
        int nl = ty + i * 8;
        float v = s[tx][nl];
        int dst = (b * Ndim + n0 + nl) * Cdim + c0 + tx;
        g_hi[dst]   = __float2half(v);
        g_netT[dst] = v;
    }
}

// ==============================================================================
// Kernel C v12: coarse kNN. 1-pass fp16 gram -> keys tile (R6-verified) ->
// 2 threads/query (disjoint 64-m halves), depth-16 register lists (32 elems,
// below the proven spill cliff) with CORRECT global index = m0 + half*64 + m.
// grid (32, 8), 256 threads (8 warps). M-tile = 128.
// ==============================================================================
#define PITCHB 272                     // 136 halves/row: conflict-free ldmatrix
#define TILEB  (128 * PITCHB)          // 34816 B per 128x128 fp16 tile
#define SM_QHI 0
#define SM_MHI TILEB
#define SM_KEY (2 * TILEB)             // 128 x 132 floats = 67584 B
#define SM_SQM (SM_KEY + 128 * 132 * 4)
#define SM_TOT (SM_SQM + 512)          // 137728 B

__device__ __forceinline__ void load_tile16(char* smem, uint32_t dst,
                                            const __half* __restrict__ src) {
    for (int i = threadIdx.x; i < 2048; i += 256) {
        int row = i >> 4, c8 = (i & 15) * 8;
        uint4 v = *(const uint4*)(src + row * Cdim + c8);
        *(uint4*)(smem + dst + row * PITCHB + c8 * 2) = v;
    }
}

// Branchless sorted insert (registers, static indices). Caller: d < kd[15].
__device__ __forceinline__ void ins16(float (&kd)[16], int (&ki)[16],
                                      float d, int m) {
    int r = 0;
    #pragma unroll
    for (int i = 0; i < 16; ++i) r += (kd[i] <= d) ? 1 : 0;
    #pragma unroll
    for (int j = 15; j > 0; --j) {
        bool sh = (j > r);
        kd[j] = sh ? kd[j - 1] : kd[j];
        ki[j] = sh ? ki[j - 1] : ki[j];
    }
    #pragma unroll
    for (int j = 0; j < 16; ++j)
        if (j == r) { kd[j] = d; ki[j] = m; }
}

__global__ __launch_bounds__(256, 1) void k_knn() {
    extern __shared__ char smem[];
    const uint32_t sbase = smem_u32(smem);
    const int tid  = threadIdx.x;
    const int lane = tid & 31;
    const int wid  = tid >> 5;          // 0..7
    const int b    = blockIdx.y;
    const int n0   = blockIdx.x * 128;
    const int qbase = wid * 16;

    // Stage Q hi tile (128 x 128 fp16) once
    load_tile16(smem, SM_QHI, g_hi + (size_t)(b * Ndim + n0) * Cdim);

    const uint32_t a_base = sbase + SM_QHI + (qbase + (lane & 15)) * PITCHB + ((lane >> 4) << 4);
    const uint32_t b_base = sbase + SM_MHI + ((lane & 7) + ((lane >> 4) << 3)) * PITCHB
                                  + (((lane >> 3) & 1) << 4);

    float* keysp = (float*)(smem + SM_KEY);
    const float* sqm = (const float*)(smem + SM_SQM);

    // scan identity: query (tid & 127), m-half (tid >> 7)
    const int sq_ = tid & 127;
    const int hf  = tid >> 7;

    float kd[16]; int ki[16];
    #pragma unroll
    for (int i = 0; i < 16; ++i) { kd[i] = FLT_MAX; ki[i] = 0; }
    float worst = FLT_MAX;

    for (int mt = 0; mt < 32; ++mt) {
        const int m0 = mt * 128;
        __syncthreads();   // previous scan done; M tile + keys reusable
        load_tile16(smem, SM_MHI, g_hi + (size_t)(b * Ndim + m0) * Cdim);
        if (tid < 128) ((float*)(smem + SM_SQM))[tid] = g_sq[b * Ndim + m0 + tid];
        __syncthreads();

        float c[16][4];
        #pragma unroll
        for (int t = 0; t < 16; ++t)
            #pragma unroll
            for (int e = 0; e < 4; ++e) c[t][e] = 0.f;

        #pragma unroll
        for (int ks = 0; ks < 8; ++ks) {
            uint32_t ra[4];
            ldmx4(ra, a_base + ks * 32);
            #pragma unroll
            for (int tp = 0; tp < 8; ++tp) {
                uint32_t rb[4];
                ldmx4(rb, b_base + tp * (16 * PITCHB) + ks * 32);
                mma16816(c[2 * tp],     ra, rb[0], rb[1]);
                mma16816(c[2 * tp + 1], ra, rb[2], rb[3]);
            }
        }

        // keys[q][m] = sq[m] - 2*dot  (unpacked, R6-verified layout)
        const int q0 = qbase + (lane >> 2);
        const int mo = (lane & 3) * 2;
        #pragma unroll
        for (int t = 0; t < 16; ++t) {
            int m = t * 8 + mo;
            float s0 = sqm[m], s1 = sqm[m + 1];
            *(float2*)&keysp[q0 * 132 + m] =
                make_float2(s0 - 2.f * c[t][0], s1 - 2.f * c[t][1]);
            *(float2*)&keysp[(q0 + 8) * 132 + m] =
                make_float2(s0 - 2.f * c[t][2], s1 - 2.f * c[t][3]);
        }
        __syncthreads();

        // coarse scan: 2 threads per query, disjoint halves, CORRECT index base
        {
            const float* krow = keysp + sq_ * 132 + hf * 64;
            const int mbase = m0 + hf * 64;   // <-- includes half offset (R8 bugfix)
            #pragma unroll 4
            for (int m = 0; m < 64; ++m) {
                float kv = krow[m];
                if (kv < worst) { ins16(kd, ki, kv, mbase + m); worst = kd[15]; }
            }
        }
    }

    {
        int* crow = g_cand + ((size_t)(b * Ndim + n0 + sq_)) * NCAND + hf * 16;
        #pragma unroll
        for (int i = 0; i < 16; ++i) crow[i] = ki[i];
    }
}

// ==============================================================================
// Kernel C2: exact fp32 rescore of 32 candidates/query + exact top-17 extract.
// grid (Ndim/8, Bsz), 256 threads: warp w handles query blockIdx.x*8 + w.
// Lane <-> candidate entry 1:1 (all 32 distinct: halves are disjoint).
// ==============================================================================
__global__ __launch_bounds__(256) void k_resc() {
    const int lane = threadIdx.x & 31;
    const int wid  = threadIdx.x >> 5;
    const int b    = blockIdx.y;
    const int q    = blockIdx.x * 8 + wid;

    const float4 qv = *(const float4*)&g_netT[(size_t)(b * Ndim + q) * Cdim + lane * 4];
    const int* crow = g_cand + ((size_t)(b * Ndim + q)) * NCAND;
    int ma = crow[lane];

    float part[NCAND];
    #pragma unroll
    for (int ci = 0; ci < NCAND; ++ci) {
        int m = __shfl_sync(FULLM, ma, ci);
        float4 mv = *(const float4*)&g_netT[(size_t)(b * Ndim + m) * Cdim + lane * 4];
        part[ci] = qv.x * mv.x + qv.y * mv.y + qv.z * mv.z + qv.w * mv.w;
    }
    #pragma unroll
    for (int ci = 0; ci < NCAND; ++ci) {
        float v = part[ci];
        v += __shfl_xor_sync(FULLM, v, 16);
        v += __shfl_xor_sync(FULLM, v, 8);
        v += __shfl_xor_sync(FULLM, v, 4);
        v += __shfl_xor_sync(FULLM, v, 2);
        v += __shfl_xor_sync(FULLM, v, 1);
        part[ci] = v;
    }
    float da = 0.f;
    #pragma unroll
    for (int ci = 0; ci < NCAND; ++ci) da = (lane == ci) ? part[ci] : da;

    float ka = __ldg(&g_sq[b * Ndim + ma]) - 2.f * da;

    int* orow = g_idx + ((size_t)(b * Ndim + q)) * KNN;
    #pragma unroll 1
    for (int t = 0; t < 17; ++t) {
        float lk = ka;
        int   lm = ma;
        #pragma unroll
        for (int d = 16; d > 0; d >>= 1) {
            float ok = __shfl_xor_sync(FULLM, lk, d);
            int   om = __shfl_xor_sync(FULLM, lm, d);
            bool take = (ok < lk) || (ok == lk && om < lm);
            lk = take ? ok : lk;
            lm = take ? om : lm;
        }
        if (t > 0 && lane == 0) orow[t - 1] = lm;   // t=0 = self (strict min) dropped
        if (ma == lm) ka = FLT_MAX;
    }
}

// ==============================================================================
// Kernel D: two independent 64-reg GEMMs selected by z&1:
//   which=0: p1   = w1@net                  -> g_p1t  [b][n][o]
//   which=1: base = (w2-w1)@net + (b1+b2)   -> g_baset[b][n][o]
// ==============================================================================
__global__ __launch_bounds__(256) void k_proj(const float* __restrict__ w1,
                                              const float* __restrict__ b1,
                                              const float* __restrict__ w2,
                                              const float* __restrict__ b2) {
    __shared__ float Wc[16][129];   // [c-chunk][o]
    __shared__ float Ns[16][128];   // [c-chunk][n]

    const int b     = blockIdx.y;
    const int n0    = blockIdx.x * 128;
    const int which = blockIdx.z & 1;
    const int oz    = (blockIdx.z >> 1) * 128;
    const int tid = threadIdx.x;
    const int tx = tid & 15;        // o group
    const int ty = tid >> 4;        // n group

    float a[8][8];
    #pragma unroll
    for (int j = 0; j < 8; ++j)
        #pragma unroll
        for (int i = 0; i < 8; ++i) a[j][i] = 0.f;

    for (int k0 = 0; k0 < 128; k0 += 16) {
        __syncthreads();
        #pragma unroll
        for (int i = 0; i < 8; ++i) {
            int idx = tid + i * 256;
            int cc = idx & 15, o = idx >> 4;
            float wv = w1[(oz + o) * 128 + k0 + cc];
            if (which) wv = w2[(oz + o) * 128 + k0 + cc] - wv;
            Wc[cc][o] = wv;
        }
        #pragma unroll
        for (int i = 0; i < 8; ++i) {
            int idx = tid + i * 256;
            int c = idx >> 7, n = idx & 127;
            Ns[c][n] = g_net[(b * 128 + k0 + c) * Ndim + n0 + n];
        }
        __syncthreads();
        #pragma unroll
        for (int kk = 0; kk < 16; ++kk) {
            float4 nv0 = *(const float4*)&Ns[kk][ty * 8];
            float4 nv1 = *(const float4*)&Ns[kk][ty * 8 + 4];
            float nr[8] = {nv0.x, nv0.y, nv0.z, nv0.w, nv1.x, nv1.y, nv1.z, nv1.w};
            float wr[8];
            #pragma unroll
            for (int i = 0; i < 8; ++i) wr[i] = Wc[kk][tx * 8 + i];
            #pragma unroll
            for (int j = 0; j < 8; ++j)
                #pragma unroll
                for (int i = 0; i < 8; ++i) a[j][i] += nr[j] * wr[i];
        }
    }

    float bb[8];
    #pragma unroll
    for (int i = 0; i < 8; ++i) {
        int o = oz + tx * 8 + i;
        bb[i] = which ? (__ldg(&b1[o]) + __ldg(&b2[o])) : 0.f;
    }
    float* dst = which ? g_baset : g_p1t;
    #pragma unroll
    for (int j = 0; j < 8; ++j) {
        int n = n0 + ty * 8 + j;
        int base = (b * Ndim + n) * Odim + oz + tx * 8;
        float4 v0 = {a[j][0] + bb[0], a[j][1] + bb[1], a[j][2] + bb[2], a[j][3] + bb[3]};
        float4 v1 = {a[j][4] + bb[4], a[j][5] + bb[5], a[j][6] + bb[6], a[j][7] + bb[7]};
        *(float4*)&dst[base]     = v0;
        *(float4*)&dst[base + 4] = v1;
    }
}

// ==============================================================================
// Kernel E: y[b,o,n] = relu(max_k (base[b,n,o] + p1t[b,idx[n,k],o]))
// ==============================================================================
__global__ __launch_bounds__(256) void k_edge(float* __restrict__ out) {
    __shared__ int   idxs[32][16];
    __shared__ float ys[32][257];

    const int b  = blockIdx.y;
    const int n0 = blockIdx.x * 32;
    const int tid = threadIdx.x;

    #pragma unroll
    for (int i = 0; i < 2; ++i) {
        int j = tid + i * 256;
        idxs[j >> 4][j & 15] = g_idx[(b * Ndim + n0 + (j >> 4)) * KNN + (j & 15)];
    }
    __syncthreads();

    #pragma unroll 1
    for (int nn = 0; nn < 32; ++nn) {
        float v = g_baset[(b * Ndim + n0 + nn) * Odim + tid];
        float acc = -FLT_MAX;
        #pragma unroll
        for (int t = 0; t < 16; ++t) {
            int m = idxs[nn][t];
            acc = fmaxf(acc, v + g_p1t[(b * Ndim + m) * Odim + tid]);
        }
        ys[nn][tid] = fmaxf(acc, 0.f);
    }
    __syncthreads();

    #pragma unroll
    for (int i = 0; i < 32; ++i) {
        int j = tid + i * 256;
        int o = j >> 5, n = j & 31;
        out[(b * Odim + o) * Ndim + n0 + n] = ys[n][o];
    }
}

// ==============================================================================
extern "C" void kernel_launch(void* const* d_in, const int* in_sizes, int n_in,
                              void* d_out, int out_size) {
    const float *x = 0, *w0 = 0, *b0 = 0, *w1 = 0, *b1 = 0, *w2 = 0, *b2 = 0;
    for (int i = 0; i < n_in; ++i) {
        const float* p = (const float*)d_in[i];
        switch (in_sizes[i]) {
            case 4194304: x = p; break;
            case 16384:   w0 = p; break;
            case 128:     b0 = p; break;
            case 32768:   if (!w1) w1 = p; else w2 = p; break;
            case 256:     if (!b1) b1 = p; else b2 = p; break;
            default: break; // k, scale scalars
        }
    }
    float* out = (float*)d_out;

    cudaFuncSetAttribute(k_knn, cudaFuncAttributeMaxDynamicSharedMemorySize, SM_TOT);

    k_net  <<<dim3(32, 8),        256>>>(x, w0, b0);
    k_split<<<dim3(128, 4, 8),    256>>>();
    k_knn  <<<dim3(32, 8),        256, SM_TOT>>>();
    k_resc <<<dim3(Ndim / 8, 8),  256>>>();
    k_proj <<<dim3(32, 8, 4),     256>>>(w1, b1, w2, b2);
    k_edge <<<dim3(128, 8),       256>>>(out);
}

// round 13
// speedup vs baseline: 21.6069x; 1.0008x over previous
#include <cuda_runtime.h>
#include <cuda_fp16.h>
#include <float.h>
#include <stdint.h>

#define Bsz  8
#define Cdim 128
#define Ndim 4096
#define Odim 256
#define KNN  16
#define NCAND 32
#define FULLM 0xFFFFFFFFu

// ---------------- scratch (static device globals; no allocations) -------------
__device__ float g_net[Bsz * Cdim * Ndim];     // [b][c][n]      16 MB
__device__ float g_sq[Bsz * Ndim];             // [b][n]
__device__ int   g_idx[Bsz * Ndim * KNN];      // [b][n][k]       2 MB
__device__ float g_p1t[Bsz * Ndim * Odim];     // [b][n][o]      32 MB
__device__ float g_baset[Bsz * Ndim * Odim];   // [b][n][o]      32 MB
__device__ __half g_hi[Bsz * Ndim * Cdim];     // [b][n][c]       8 MB
__device__ float g_netT[Bsz * Ndim * Cdim];    // [b][n][c]      16 MB
__device__ int   g_cand[Bsz * Ndim * NCAND];   // coarse candidate indices

__device__ __forceinline__ uint32_t smem_u32(const void* p) {
    uint32_t a;
    asm("{ .reg .u64 t; cvta.to.shared.u64 t, %1; cvt.u32.u64 %0, t; }" : "=r"(a) : "l"(p));
    return a;
}
__device__ __forceinline__ void ldmx4(uint32_t* r, uint32_t addr) {
    asm volatile("ldmatrix.sync.aligned.m8n8.x4.shared.b16 {%0,%1,%2,%3}, [%4];"
        : "=r"(r[0]), "=r"(r[1]), "=r"(r[2]), "=r"(r[3]) : "r"(addr));
}
__device__ __forceinline__ void mma16816(float* c, const uint32_t* a,
                                         uint32_t b0, uint32_t b1) {
    asm volatile("mma.sync.aligned.m16n8k16.row.col.f32.f16.f16.f32 "
        "{%0,%1,%2,%3}, {%4,%5,%6,%7}, {%8,%9}, {%0,%1,%2,%3};"
        : "+f"(c[0]), "+f"(c[1]), "+f"(c[2]), "+f"(c[3])
        : "r"(a[0]), "r"(a[1]), "r"(a[2]), "r"(a[3]), "r"(b0), "r"(b1));
}

// ==============================================================================
// Kernel A: net = relu(w0 @ x + b0), fused sq[b][n] = sum_c net^2
// ==============================================================================
__global__ __launch_bounds__(256) void k_net(const float* __restrict__ x,
                                             const float* __restrict__ w0,
                                             const float* __restrict__ b0) {
    __shared__ float Ws[32][129];
    __shared__ float Ns[32][128];
    __shared__ float sqs[16][129];

    const int b  = blockIdx.y;
    const int n0 = blockIdx.x * 128;
    const int tid = threadIdx.x;
    const int tx = tid & 15;
    const int ty = tid >> 4;

    float acc[8][8];
    #pragma unroll
    for (int i = 0; i < 8; ++i)
        #pragma unroll
        for (int j = 0; j < 8; ++j) acc[i][j] = 0.f;

    for (int k0 = 0; k0 < 128; k0 += 32) {
        __syncthreads();
        #pragma unroll
        for (int i = 0; i < 16; ++i) {
            int idx = tid + i * 256;
            int cc = idx & 31, o = idx >> 5;
            Ws[cc][o] = w0[o * 128 + k0 + cc];
        }
        #pragma unroll
        for (int i = 0; i < 16; ++i) {
            int idx = tid + i * 256;
            int c = idx >> 7, n = idx & 127;
            Ns[c][n] = x[(b * 128 + k0 + c) * Ndim + n0 + n];
        }
        __syncthreads();
        #pragma unroll
        for (int kk = 0; kk < 32; ++kk) {
            float4 x0 = *(const float4*)&Ns[kk][tx * 8];
            float4 x1 = *(const float4*)&Ns[kk][tx * 8 + 4];
            float xr[8] = {x0.x, x0.y, x0.z, x0.w, x1.x, x1.y, x1.z, x1.w};
            #pragma unroll
            for (int i = 0; i < 8; ++i) {
                float wv = Ws[kk][ty * 8 + i];
                #pragma unroll
                for (int j = 0; j < 8; ++j) acc[i][j] += wv * xr[j];
            }
        }
    }

    float part[8];
    #pragma unroll
    for (int j = 0; j < 8; ++j) part[j] = 0.f;

    #pragma unroll
    for (int i = 0; i < 8; ++i) {
        int o = ty * 8 + i;
        float bv = __ldg(&b0[o]);
        float r[8];
        #pragma unroll
        for (int j = 0; j < 8; ++j) {
            r[j] = fmaxf(acc[i][j] + bv, 0.f);
            part[j] += r[j] * r[j];
        }
        int base = (b * 128 + o) * Ndim + n0 + tx * 8;
        float4 s0 = {r[0], r[1], r[2], r[3]};
        float4 s1 = {r[4], r[5], r[6], r[7]};
        *(float4*)&g_net[base]     = s0;
        *(float4*)&g_net[base + 4] = s1;
    }
    #pragma unroll
    for (int j = 0; j < 8; ++j) sqs[ty][tx * 8 + j] = part[j];
    __syncthreads();
    if (tid < 128) {
        float s = 0.f;
        #pragma unroll
        for (int r = 0; r < 16; ++r) s += sqs[r][tid];
        g_sq[b * Ndim + n0 + tid] = s;
    }
}

// ==============================================================================
// Kernel B: transpose: g_net[b][c][n] -> g_hi (fp16) and g_netT (fp32), [b][n][c]
// ==============================================================================
__global__ __launch_bounds__(256) void k_split() {
    __shared__ float s[32][33];
    const int b  = blockIdx.z;
    const int c0 = blockIdx.y * 32;
    const int n0 = blockIdx.x * 32;
    const int tx = threadIdx.x & 31;
    const int ty = threadIdx.x >> 5;    // 0..7

    #pragma unroll
    for (int i = 0; i < 4; ++i) {
        int c = ty + i * 8;
        s[c][tx] = g_net[(b * Cdim + c0 + c) * Ndim + n0 + tx];
    }
    __syncthreads();
    #pragma unroll
    for (int i = 0; i < 4; ++i) {
        int nl = ty + i * 8;
        float v = s[tx][nl];
        int dst = (b * Ndim + n0 + nl) * Cdim + c0 + tx;
        g_hi[dst]   = __float2half(v);
        g_netT[dst] = v;
    }
}

// ==============================================================================
// Kernel C v12: coarse kNN. 1-pass fp16 gram -> keys tile (R6-verified) ->
// 2 threads/query (disjoint 64-m halves), depth-16 register lists (32 elems,
// below the proven spill cliff) with CORRECT global index = m0 + half*64 + m.
// grid (32, 8), 256 threads (8 warps). M-tile = 128.
// ==============================================================================
#define PITCHB 272                     // 136 halves/row: conflict-free ldmatrix
#define TILEB  (128 * PITCHB)          // 34816 B per 128x128 fp16 tile
#define SM_QHI 0
#define SM_MHI TILEB
#define SM_KEY (2 * TILEB)             // 128 x 132 floats = 67584 B
#define SM_SQM (SM_KEY + 128 * 132 * 4)
#define SM_TOT (SM_SQM + 512)          // 137728 B

__device__ __forceinline__ void load_tile16(char* smem, uint32_t dst,
                                            const __half* __restrict__ src) {
    for (int i = threadIdx.x; i < 2048; i += 256) {
        int row = i >> 4, c8 = (i & 15) * 8;
        uint4 v = *(const uint4*)(src + row * Cdim + c8);
        *(uint4*)(smem + dst + row * PITCHB + c8 * 2) = v;
    }
}

// Branchless sorted insert (registers, static indices). Caller: d < kd[15].
__device__ __forceinline__ void ins16(float (&kd)[16], int (&ki)[16],
                                      float d, int m) {
    int r = 0;
    #pragma unroll
    for (int i = 0; i < 16; ++i) r += (kd[i] <= d) ? 1 : 0;
    #pragma unroll
    for (int j = 15; j > 0; --j) {
        bool sh = (j > r);
        kd[j] = sh ? kd[j - 1] : kd[j];
        ki[j] = sh ? ki[j - 1] : ki[j];
    }
    #pragma unroll
    for (int j = 0; j < 16; ++j)
        if (j == r) { kd[j] = d; ki[j] = m; }
}

__global__ __launch_bounds__(256, 1) void k_knn() {
    extern __shared__ char smem[];
    const uint32_t sbase = smem_u32(smem);
    const int tid  = threadIdx.x;
    const int lane = tid & 31;
    const int wid  = tid >> 5;          // 0..7
    const int b    = blockIdx.y;
    const int n0   = blockIdx.x * 128;
    const int qbase = wid * 16;

    // Stage Q hi tile (128 x 128 fp16) once
    load_tile16(smem, SM_QHI, g_hi + (size_t)(b * Ndim + n0) * Cdim);

    const uint32_t a_base = sbase + SM_QHI + (qbase + (lane & 15)) * PITCHB + ((lane >> 4) << 4);
    const uint32_t b_base = sbase + SM_MHI + ((lane & 7) + ((lane >> 4) << 3)) * PITCHB
                                  + (((lane >> 3) & 1) << 4);

    float* keysp = (float*)(smem + SM_KEY);
    const float* sqm = (const float*)(smem + SM_SQM);

    // scan identity: query (tid & 127), m-half (tid >> 7)
    const int sq_ = tid & 127;
    const int hf  = tid >> 7;

    float kd[16]; int ki[16];
    #pragma unroll
    for (int i = 0; i < 16; ++i) { kd[i] = FLT_MAX; ki[i] = 0; }
    float worst = FLT_MAX;

    for (int mt = 0; mt < 32; ++mt) {
        const int m0 = mt * 128;
        __syncthreads();   // previous scan done; M tile + keys reusable
        load_tile16(smem, SM_MHI, g_hi + (size_t)(b * Ndim + m0) * Cdim);
        if (tid < 128) ((float*)(smem + SM_SQM))[tid] = g_sq[b * Ndim + m0 + tid];
        __syncthreads();

        float c[16][4];
        #pragma unroll
        for (int t = 0; t < 16; ++t)
            #pragma unroll
            for (int e = 0; e < 4; ++e) c[t][e] = 0.f;

        #pragma unroll
        for (int ks = 0; ks < 8; ++ks) {
            uint32_t ra[4];
            ldmx4(ra, a_base + ks * 32);
            #pragma unroll
            for (int tp = 0; tp < 8; ++tp) {
                uint32_t rb[4];
                ldmx4(rb, b_base + tp * (16 * PITCHB) + ks * 32);
                mma16816(c[2 * tp],     ra, rb[0], rb[1]);
                mma16816(c[2 * tp + 1], ra, rb[2], rb[3]);
            }
        }

        // keys[q][m] = sq[m] - 2*dot  (unpacked, R6-verified layout)
        const int q0 = qbase + (lane >> 2);
        const int mo = (lane & 3) * 2;
        #pragma unroll
        for (int t = 0; t < 16; ++t) {
            int m = t * 8 + mo;
            float s0 = sqm[m], s1 = sqm[m + 1];
            *(float2*)&keysp[q0 * 132 + m] =
                make_float2(s0 - 2.f * c[t][0], s1 - 2.f * c[t][1]);
            *(float2*)&keysp[(q0 + 8) * 132 + m] =
                make_float2(s0 - 2.f * c[t][2], s1 - 2.f * c[t][3]);
        }
        __syncthreads();

        // coarse scan: 2 threads per query, disjoint halves, CORRECT index base
        {
            const float* krow = keysp + sq_ * 132 + hf * 64;
            const int mbase = m0 + hf * 64;   // <-- includes half offset (R8 bugfix)
            #pragma unroll 4
            for (int m = 0; m < 64; ++m) {
                float kv = krow[m];
                if (kv < worst) { ins16(kd, ki, kv, mbase + m); worst = kd[15]; }
            }
        }
    }

    {
        int* crow = g_cand + ((size_t)(b * Ndim + n0 + sq_)) * NCAND + hf * 16;
        #pragma unroll
        for (int i = 0; i < 16; ++i) crow[i] = ki[i];
    }
}

// ==============================================================================
// Kernel C2: exact fp32 rescore of 32 candidates/query + exact top-17 extract.
// grid (Ndim/8, Bsz), 256 threads: warp w handles query blockIdx.x*8 + w.
// Lane <-> candidate entry 1:1 (all 32 distinct: halves are disjoint).
// ==============================================================================
__global__ __launch_bounds__(256) void k_resc() {
    const int lane = threadIdx.x & 31;
    const int wid  = threadIdx.x >> 5;
    const int b    = blockIdx.y;
    const int q    = blockIdx.x * 8 + wid;

    const float4 qv = *(const float4*)&g_netT[(size_t)(b * Ndim + q) * Cdim + lane * 4];
    const int* crow = g_cand + ((size_t)(b * Ndim + q)) * NCAND;
    int ma = crow[lane];

    float part[NCAND];
    #pragma unroll
    for (int ci = 0; ci < NCAND; ++ci) {
        int m = __shfl_sync(FULLM, ma, ci);
        float4 mv = *(const float4*)&g_netT[(size_t)(b * Ndim + m) * Cdim + lane * 4];
        part[ci] = qv.x * mv.x + qv.y * mv.y + qv.z * mv.z + qv.w * mv.w;
    }
    #pragma unroll
    for (int ci = 0; ci < NCAND; ++ci) {
        float v = part[ci];
        v += __shfl_xor_sync(FULLM, v, 16);
        v += __shfl_xor_sync(FULLM, v, 8);
        v += __shfl_xor_sync(FULLM, v, 4);
        v += __shfl_xor_sync(FULLM, v, 2);
        v += __shfl_xor_sync(FULLM, v, 1);
        part[ci] = v;
    }
    float da = 0.f;
    #pragma unroll
    for (int ci = 0; ci < NCAND; ++ci) da = (lane == ci) ? part[ci] : da;

    float ka = __ldg(&g_sq[b * Ndim + ma]) - 2.f * da;

    int* orow = g_idx + ((size_t)(b * Ndim + q)) * KNN;
    #pragma unroll 1
    for (int t = 0; t < 17; ++t) {
        float lk = ka;
        int   lm = ma;
        #pragma unroll
        for (int d = 16; d > 0; d >>= 1) {
            float ok = __shfl_xor_sync(FULLM, lk, d);
            int   om = __shfl_xor_sync(FULLM, lm, d);
            bool take = (ok < lk) || (ok == lk && om < lm);
            lk = take ? ok : lk;
            lm = take ? om : lm;
        }
        if (t > 0 && lane == 0) orow[t - 1] = lm;   // t=0 = self (strict min) dropped
        if (ma == lm) ka = FLT_MAX;
    }
}

// ==============================================================================
// Kernel D: two independent 64-reg GEMMs selected by z&1:
//   which=0: p1   = w1@net                  -> g_p1t  [b][n][o]
//   which=1: base = (w2-w1)@net + (b1+b2)   -> g_baset[b][n][o]
// ==============================================================================
__global__ __launch_bounds__(256) void k_proj(const float* __restrict__ w1,
                                              const float* __restrict__ b1,
                                              const float* __restrict__ w2,
                                              const float* __restrict__ b2) {
    __shared__ float Wc[16][129];   // [c-chunk][o]
    __shared__ float Ns[16][128];   // [c-chunk][n]

    const int b     = blockIdx.y;
    const int n0    = blockIdx.x * 128;
    const int which = blockIdx.z & 1;
    const int oz    = (blockIdx.z >> 1) * 128;
    const int tid = threadIdx.x;
    const int tx = tid & 15;        // o group
    const int ty = tid >> 4;        // n group

    float a[8][8];
    #pragma unroll
    for (int j = 0; j < 8; ++j)
        #pragma unroll
        for (int i = 0; i < 8; ++i) a[j][i] = 0.f;

    for (int k0 = 0; k0 < 128; k0 += 16) {
        __syncthreads();
        #pragma unroll
        for (int i = 0; i < 8; ++i) {
            int idx = tid + i * 256;
            int cc = idx & 15, o = idx >> 4;
            float wv = w1[(oz + o) * 128 + k0 + cc];
            if (which) wv = w2[(oz + o) * 128 + k0 + cc] - wv;
            Wc[cc][o] = wv;
        }
        #pragma unroll
        for (int i = 0; i < 8; ++i) {
            int idx = tid + i * 256;
            int c = idx >> 7, n = idx & 127;
            Ns[c][n] = g_net[(b * 128 + k0 + c) * Ndim + n0 + n];
        }
        __syncthreads();
        #pragma unroll
        for (int kk = 0; kk < 16; ++kk) {
            float4 nv0 = *(const float4*)&Ns[kk][ty * 8];
            float4 nv1 = *(const float4*)&Ns[kk][ty * 8 + 4];
            float nr[8] = {nv0.x, nv0.y, nv0.z, nv0.w, nv1.x, nv1.y, nv1.z, nv1.w};
            float wr[8];
            #pragma unroll
            for (int i = 0; i < 8; ++i) wr[i] = Wc[kk][tx * 8 + i];
            #pragma unroll
            for (int j = 0; j < 8; ++j)
                #pragma unroll
                for (int i = 0; i < 8; ++i) a[j][i] += nr[j] * wr[i];
        }
    }

    float bb[8];
    #pragma unroll
    for (int i = 0; i < 8; ++i) {
        int o = oz + tx * 8 + i;
        bb[i] = which ? (__ldg(&b1[o]) + __ldg(&b2[o])) : 0.f;
    }
    float* dst = which ? g_baset : g_p1t;
    #pragma unroll
    for (int j = 0; j < 8; ++j) {
        int n = n0 + ty * 8 + j;
        int base = (b * Ndim + n) * Odim + oz + tx * 8;
        float4 v0 = {a[j][0] + bb[0], a[j][1] + bb[1], a[j][2] + bb[2], a[j][3] + bb[3]};
        float4 v1 = {a[j][4] + bb[4], a[j][5] + bb[5], a[j][6] + bb[6], a[j][7] + bb[7]};
        *(float4*)&dst[base]     = v0;
        *(float4*)&dst[base + 4] = v1;
    }
}

// ==============================================================================
// Kernel E: y[b,o,n] = relu(max_k (base[b,n,o] + p1t[b,idx[n,k],o]))
// ==============================================================================
__global__ __launch_bounds__(256) void k_edge(float* __restrict__ out) {
    __shared__ int   idxs[32][16];
    __shared__ float ys[32][257];

    const int b  = blockIdx.y;
    const int n0 = blockIdx.x * 32;
    const int tid = threadIdx.x;

    #pragma unroll
    for (int i = 0; i < 2; ++i) {
        int j = tid + i * 256;
        idxs[j >> 4][j & 15] = g_idx[(b * Ndim + n0 + (j >> 4)) * KNN + (j & 15)];
    }
    __syncthreads();

    #pragma unroll 1
    for (int nn = 0; nn < 32; ++nn) {
        float v = g_baset[(b * Ndim + n0 + nn) * Odim + tid];
        float acc = -FLT_MAX;
        #pragma unroll
        for (int t = 0; t < 16; ++t) {
            int m = idxs[nn][t];
            acc = fmaxf(acc, v + g_p1t[(b * Ndim + m) * Odim + tid]);
        }
        ys[nn][tid] = fmaxf(acc, 0.f);
    }
    __syncthreads();

    #pragma unroll
    for (int i = 0; i < 32; ++i) {
        int j = tid + i * 256;
        int o = j >> 5, n = j & 31;
        out[(b * Odim + o) * Ndim + n0 + n] = ys[n][o];
    }
}

// ==============================================================================
extern "C" void kernel_launch(void* const* d_in, const int* in_sizes, int n_in,
                              void* d_out, int out_size) {
    const float *x = 0, *w0 = 0, *b0 = 0, *w1 = 0, *b1 = 0, *w2 = 0, *b2 = 0;
    for (int i = 0; i < n_in; ++i) {
        const float* p = (const float*)d_in[i];
        switch (in_sizes[i]) {
            case 4194304: x = p; break;
            case 16384:   w0 = p; break;
            case 128:     b0 = p; break;
            case 32768:   if (!w1) w1 = p; else w2 = p; break;
            case 256:     if (!b1) b1 = p; else b2 = p; break;
            default: break; // k, scale scalars
        }
    }
    float* out = (float*)d_out;

    cudaFuncSetAttribute(k_knn, cudaFuncAttributeMaxDynamicSharedMemorySize, SM_TOT);

    k_net  <<<dim3(32, 8),        256>>>(x, w0, b0);
    k_split<<<dim3(128, 4, 8),    256>>>();
    k_knn  <<<dim3(32, 8),        256, SM_TOT>>>();
    k_resc <<<dim3(Ndim / 8, 8),  256>>>();
    k_proj <<<dim3(32, 8, 4),     256>>>(w1, b1, w2, b2);
    k_edge <<<dim3(128, 8),       256>>>(out);
}

// round 15
// speedup vs baseline: 21.6256x; 1.0009x over previous
#include <cuda_runtime.h>
#include <cuda_fp16.h>
#include <float.h>
#include <stdint.h>

#define Bsz  8
#define Cdim 128
#define Ndim 4096
#define Odim 256
#define KNN  16
#define NCAND 32
#define FULLM 0xFFFFFFFFu

// ---------------- scratch (static device globals; no allocations) -------------
__device__ float g_net[Bsz * Cdim * Ndim];     // [b][c][n]      16 MB
__device__ float g_sq[Bsz * Ndim];             // [b][n]
__device__ int   g_idx[Bsz * Ndim * KNN];      // [b][n][k]       2 MB
__device__ float g_p1t[Bsz * Ndim * Odim];     // [b][n][o]      32 MB
__device__ float g_baset[Bsz * Ndim * Odim];   // [b][n][o]      32 MB
__device__ __half g_hi[Bsz * Ndim * Cdim];     // [b][n][c]       8 MB
__device__ float g_netT[Bsz * Ndim * Cdim];    // [b][n][c]      16 MB
__device__ int   g_cand[Bsz * Ndim * NCAND];   // coarse candidate indices

__device__ __forceinline__ uint32_t smem_u32(const void* p) {
    uint32_t a;
    asm("{ .reg .u64 t; cvta.to.shared.u64 t, %1; cvt.u32.u64 %0, t; }" : "=r"(a) : "l"(p));
    return a;
}
__device__ __forceinline__ void ldmx4(uint32_t* r, uint32_t addr) {
    asm volatile("ldmatrix.sync.aligned.m8n8.x4.shared.b16 {%0,%1,%2,%3}, [%4];"
        : "=r"(r[0]), "=r"(r[1]), "=r"(r[2]), "=r"(r[3]) : "r"(addr));
}
__device__ __forceinline__ void mma16816(float* c, const uint32_t* a,
                                         uint32_t b0, uint32_t b1) {
    asm volatile("mma.sync.aligned.m16n8k16.row.col.f32.f16.f16.f32 "
        "{%0,%1,%2,%3}, {%4,%5,%6,%7}, {%8,%9}, {%0,%1,%2,%3};"
        : "+f"(c[0]), "+f"(c[1]), "+f"(c[2]), "+f"(c[3])
        : "r"(a[0]), "r"(a[1]), "r"(a[2]), "r"(a[3]), "r"(b0), "r"(b1));
}

// ==============================================================================
// Kernel A: net = relu(w0 @ x + b0), fused sq[b][n] = sum_c net^2
// ==============================================================================
__global__ __launch_bounds__(256) void k_net(const float* __restrict__ x,
                                             const float* __restrict__ w0,
                                             const float* __restrict__ b0) {
    __shared__ float Ws[32][129];
    __shared__ float Ns[32][128];
    __shared__ float sqs[16][129];

    const int b  = blockIdx.y;
    const int n0 = blockIdx.x * 128;
    const int tid = threadIdx.x;
    const int tx = tid & 15;
    const int ty = tid >> 4;

    float acc[8][8];
    #pragma unroll
    for (int i = 0; i < 8; ++i)
        #pragma unroll
        for (int j = 0; j < 8; ++j) acc[i][j] = 0.f;

    for (int k0 = 0; k0 < 128; k0 += 32) {
        __syncthreads();
        #pragma unroll
        for (int i = 0; i < 16; ++i) {
            int idx = tid + i * 256;
            int cc = idx & 31, o = idx >> 5;
            Ws[cc][o] = w0[o * 128 + k0 + cc];
        }
        #pragma unroll
        for (int i = 0; i < 16; ++i) {
            int idx = tid + i * 256;
            int c = idx >> 7, n = idx & 127;
            Ns[c][n] = x[(b * 128 + k0 + c) * Ndim + n0 + n];
        }
        __syncthreads();
        #pragma unroll
        for (int kk = 0; kk < 32; ++kk) {
            float4 x0 = *(const float4*)&Ns[kk][tx * 8];
            float4 x1 = *(const float4*)&Ns[kk][tx * 8 + 4];
            float xr[8] = {x0.x, x0.y, x0.z, x0.w, x1.x, x1.y, x1.z, x1.w};
            #pragma unroll
            for (int i = 0; i < 8; ++i) {
                float wv = Ws[kk][ty * 8 + i];
                #pragma unroll
                for (int j = 0; j < 8; ++j) acc[i][j] += wv * xr[j];
            }
        }
    }

    float part[8];
    #pragma unroll
    for (int j = 0; j < 8; ++j) part[j] = 0.f;

    #pragma unroll
    for (int i = 0; i < 8; ++i) {
        int o = ty * 8 + i;
        float bv = __ldg(&b0[o]);
        float r[8];
        #pragma unroll
        for (int j = 0; j < 8; ++j) {
            r[j] = fmaxf(acc[i][j] + bv, 0.f);
            part[j] += r[j] * r[j];
        }
        int base = (b * 128 + o) * Ndim + n0 + tx * 8;
        float4 s0 = {r[0], r[1], r[2], r[3]};
        float4 s1 = {r[4], r[5], r[6], r[7]};
        *(float4*)&g_net[base]     = s0;
        *(float4*)&g_net[base + 4] = s1;
    }
    #pragma unroll
    for (int j = 0; j < 8; ++j) sqs[ty][tx * 8 + j] = part[j];
    __syncthreads();
    if (tid < 128) {
        float s = 0.f;
        #pragma unroll
        for (int r = 0; r < 16; ++r) s += sqs[r][tid];
        g_sq[b * Ndim + n0 + tid] = s;
    }
}

// ==============================================================================
// Kernel B: transpose: g_net[b][c][n] -> g_hi (fp16) and g_netT (fp32), [b][n][c]
// ==============================================================================
__global__ __launch_bounds__(256) void k_split() {
    __shared__ float s[32][33];
    const int b  = blockIdx.z;
    const int c0 = blockIdx.y * 32;
    const int n0 = blockIdx.x * 32;
    const int tx = threadIdx.x & 31;
    const int ty = threadIdx.x >> 5;    // 0..7

    #pragma unroll
    for (int i = 0; i < 4; ++i) {
        int c = ty + i * 8;
        s[c][tx] = g_net[(b * Cdim + c0 + c) * Ndim + n0 + tx];
    }
    __syncthreads();
    #pragma unroll
    for (int i = 0; i < 4; ++i) {
        int nl = ty + i * 8;
        float v = s[tx][nl];
        int dst = (b * Ndim + n0 + nl) * Cdim + c0 + tx;
        g_hi[dst]   = __float2half(v);
        g_netT[dst] = v;
    }
}

// ==============================================================================
// Kernel C v15: coarse kNN. 1-pass fp16 gram, DOUBLE-BUFFERED M tiles (next
// tile's loads issued before the scan so LDG latency hides under scan work),
// keys tile -> 2 threads/query depth-16 register lists -> g_cand.
// grid (32, 8), 256 threads (8 warps). M-tile = 128.
// ==============================================================================
#define PITCHB 272                     // 136 halves/row: conflict-free ldmatrix
#define TILEB  (128 * PITCHB)          // 34816 B per 128x128 fp16 tile
#define SM_QHI 0
#define SM_MH0 TILEB                   // M buffer 0
#define SM_MH1 (2 * TILEB)             // M buffer 1
#define SM_KEY (3 * TILEB)             // 128 x 132 floats = 67584 B
#define SM_SQ0 (SM_KEY + 128 * 132 * 4)
#define SM_SQ1 (SM_SQ0 + 512)
#define SM_TOT (SM_SQ1 + 512)          // 173568 B

__device__ __forceinline__ void load_tile16(char* smem, uint32_t dst,
                                            const __half* __restrict__ src) {
    for (int i = threadIdx.x; i < 2048; i += 256) {
        int row = i >> 4, c8 = (i & 15) * 8;
        uint4 v = *(const uint4*)(src + row * Cdim + c8);
        *(uint4*)(smem + dst + row * PITCHB + c8 * 2) = v;
    }
}

// Branchless sorted insert (registers, static indices). Caller: d < kd[15].
__device__ __forceinline__ void ins16(float (&kd)[16], int (&ki)[16],
                                      float d, int m) {
    int r = 0;
    #pragma unroll
    for (int i = 0; i < 16; ++i) r += (kd[i] <= d) ? 1 : 0;
    #pragma unroll
    for (int j = 15; j > 0; --j) {
        bool sh = (j > r);
        kd[j] = sh ? kd[j - 1] : kd[j];
        ki[j] = sh ? ki[j - 1] : ki[j];
    }
    #pragma unroll
    for (int j = 0; j < 16; ++j)
        if (j == r) { kd[j] = d; ki[j] = m; }
}

__global__ __launch_bounds__(256, 1) void k_knn() {
    extern __shared__ char smem[];
    const uint32_t sbase = smem_u32(smem);
    const int tid  = threadIdx.x;
    const int lane = tid & 31;
    const int wid  = tid >> 5;          // 0..7
    const int b    = blockIdx.y;
    const int n0   = blockIdx.x * 128;
    const int qbase = wid * 16;

    // Stage Q hi tile + first M tile
    load_tile16(smem, SM_QHI, g_hi + (size_t)(b * Ndim + n0) * Cdim);
    load_tile16(smem, SM_MH0, g_hi + (size_t)(b * Ndim) * Cdim);
    if (tid < 128) ((float*)(smem + SM_SQ0))[tid] = g_sq[b * Ndim + tid];
    __syncthreads();

    const uint32_t a_base = sbase + SM_QHI + (qbase + (lane & 15)) * PITCHB + ((lane >> 4) << 4);
    const uint32_t b_base0 = sbase + SM_MH0 + ((lane & 7) + ((lane >> 4) << 3)) * PITCHB
                                   + (((lane >> 3) & 1) << 4);

    float* keysp = (float*)(smem + SM_KEY);

    // scan identity: query (tid & 127), m-half (tid >> 7)
    const int sq_ = tid & 127;
    const int hf  = tid >> 7;

    float kd[16]; int ki[16];
    #pragma unroll
    for (int i = 0; i < 16; ++i) { kd[i] = FLT_MAX; ki[i] = 0; }
    float worst = FLT_MAX;

    for (int mt = 0; mt < 32; ++mt) {
        const int m0 = mt * 128;
        const int buf = mt & 1;
        const float* sqm = (const float*)(smem + SM_SQ0 + buf * 512);

        float c[16][4];
        #pragma unroll
        for (int t = 0; t < 16; ++t)
            #pragma unroll
            for (int e = 0; e < 4; ++e) c[t][e] = 0.f;

        const uint32_t bb = b_base0 + buf * TILEB;
        #pragma unroll
        for (int ks = 0; ks < 8; ++ks) {
            uint32_t ra[4];
            ldmx4(ra, a_base + ks * 32);
            #pragma unroll
            for (int tp = 0; tp < 8; ++tp) {
                uint32_t rb[4];
                ldmx4(rb, bb + tp * (16 * PITCHB) + ks * 32);
                mma16816(c[2 * tp],     ra, rb[0], rb[1]);
                mma16816(c[2 * tp + 1], ra, rb[2], rb[3]);
            }
        }

        // keys[q][m] = sq[m] - 2*dot  (unpacked, verified layout)
        const int q0 = qbase + (lane >> 2);
        const int mo = (lane & 3) * 2;
        #pragma unroll
        for (int t = 0; t < 16; ++t) {
            int m = t * 8 + mo;
            float s0 = sqm[m], s1 = sqm[m + 1];
            *(float2*)&keysp[q0 * 132 + m] =
                make_float2(s0 - 2.f * c[t][0], s1 - 2.f * c[t][1]);
            *(float2*)&keysp[(q0 + 8) * 132 + m] =
                make_float2(s0 - 2.f * c[t][2], s1 - 2.f * c[t][3]);
        }
        __syncthreads();   // keys visible; all reads of M[buf] complete

        // prefetch next M tile into the other buffer (overlaps with scan)
        if (mt < 31) {
            load_tile16(smem, SM_MH0 + (1 - buf) * TILEB,
                        g_hi + (size_t)(b * Ndim + m0 + 128) * Cdim);
            if (tid < 128)
                ((float*)(smem + SM_SQ0 + (1 - buf) * 512))[tid] =
                    g_sq[b * Ndim + m0 + 128 + tid];
        }

        // coarse scan: 2 threads per query, disjoint halves
        {
            const float* krow = keysp + sq_ * 132 + hf * 64;
            const int mbase = m0 + hf * 64;
            #pragma unroll 4
            for (int m = 0; m < 64; ++m) {
                float kv = krow[m];
                if (kv < worst) { ins16(kd, ki, kv, mbase + m); worst = kd[15]; }
            }
        }
        __syncthreads();   // scan done (keys free) AND next M tile resident
    }

    {
        int* crow = g_cand + ((size_t)(b * Ndim + n0 + sq_)) * NCAND + hf * 16;
        #pragma unroll
        for (int i = 0; i < 16; ++i) crow[i] = ki[i];
    }
}

// ==============================================================================
// Kernel C2: exact fp32 rescore of 32 candidates/query + exact top-17 extract.
// grid (Ndim/8, Bsz), 256 threads: warp w handles query blockIdx.x*8 + w.
// ==============================================================================
__global__ __launch_bounds__(256) void k_resc() {
    const int lane = threadIdx.x & 31;
    const int wid  = threadIdx.x >> 5;
    const int b    = blockIdx.y;
    const int q    = blockIdx.x * 8 + wid;

    const float4 qv = *(const float4*)&g_netT[(size_t)(b * Ndim + q) * Cdim + lane * 4];
    const int* crow = g_cand + ((size_t)(b * Ndim + q)) * NCAND;
    int ma = crow[lane];

    float part[NCAND];
    #pragma unroll
    for (int ci = 0; ci < NCAND; ++ci) {
        int m = __shfl_sync(FULLM, ma, ci);
        float4 mv = *(const float4*)&g_netT[(size_t)(b * Ndim + m) * Cdim + lane * 4];
        part[ci] = qv.x * mv.x + qv.y * mv.y + qv.z * mv.z + qv.w * mv.w;
    }
    #pragma unroll
    for (int ci = 0; ci < NCAND; ++ci) {
        float v = part[ci];
        v += __shfl_xor_sync(FULLM, v, 16);
        v += __shfl_xor_sync(FULLM, v, 8);
        v += __shfl_xor_sync(FULLM, v, 4);
        v += __shfl_xor_sync(FULLM, v, 2);
        v += __shfl_xor_sync(FULLM, v, 1);
        part[ci] = v;
    }
    float da = 0.f;
    #pragma unroll
    for (int ci = 0; ci < NCAND; ++ci) da = (lane == ci) ? part[ci] : da;

    float ka = __ldg(&g_sq[b * Ndim + ma]) - 2.f * da;

    int* orow = g_idx + ((size_t)(b * Ndim + q)) * KNN;
    #pragma unroll 1
    for (int t = 0; t < 17; ++t) {
        float lk = ka;
        int   lm = ma;
        #pragma unroll
        for (int d = 16; d > 0; d >>= 1) {
            float ok = __shfl_xor_sync(FULLM, lk, d);
            int   om = __shfl_xor_sync(FULLM, lm, d);
            bool take = (ok < lk) || (ok == lk && om < lm);
            lk = take ? ok : lk;
            lm = take ? om : lm;
        }
        if (t > 0 && lane == 0) orow[t - 1] = lm;   // t=0 = self (strict min) dropped
        if (ma == lm) ka = FLT_MAX;
    }
}

// ==============================================================================
// Kernel D: two independent 64-reg GEMMs selected by z&1:
//   which=0: p1   = w1@net                  -> g_p1t  [b][n][o]
//   which=1: base = (w2-w1)@net + (b1+b2)   -> g_baset[b][n][o]
// ==============================================================================
__global__ __launch_bounds__(256) void k_proj(const float* __restrict__ w1,
                                              const float* __restrict__ b1,
                                              const float* __restrict__ w2,
                                              const float* __restrict__ b2) {
    __shared__ float Wc[16][129];   // [c-chunk][o]
    __shared__ float Ns[16][128];   // [c-chunk][n]

    const int b     = blockIdx.y;
    const int n0    = blockIdx.x * 128;
    const int which = blockIdx.z & 1;
    const int oz    = (blockIdx.z >> 1) * 128;
    const int tid = threadIdx.x;
    const int tx = tid & 15;        // o group
    const int ty = tid >> 4;        // n group

    float a[8][8];
    #pragma unroll
    for (int j = 0; j < 8; ++j)
        #pragma unroll
        for (int i = 0; i < 8; ++i) a[j][i] = 0.f;

    for (int k0 = 0; k0 < 128; k0 += 16) {
        __syncthreads();
        #pragma unroll
        for (int i = 0; i < 8; ++i) {
            int idx = tid + i * 256;
            int cc = idx & 15, o = idx >> 4;
            float wv = w1[(oz + o) * 128 + k0 + cc];
            if (which) wv = w2[(oz + o) * 128 + k0 + cc] - wv;
            Wc[cc][o] = wv;
        }
        #pragma unroll
        for (int i = 0; i < 8; ++i) {
            int idx = tid + i * 256;
            int c = idx >> 7, n = idx & 127;
            Ns[c][n] = g_net[(b * 128 + k0 + c) * Ndim + n0 + n];
        }
        __syncthreads();
        #pragma unroll
        for (int kk = 0; kk < 16; ++kk) {
            float4 nv0 = *(const float4*)&Ns[kk][ty * 8];
            float4 nv1 = *(const float4*)&Ns[kk][ty * 8 + 4];
            float nr[8] = {nv0.x, nv0.y, nv0.z, nv0.w, nv1.x, nv1.y, nv1.z, nv1.w};
            float wr[8];
            #pragma unroll
            for (int i = 0; i < 8; ++i) wr[i] = Wc[kk][tx * 8 + i];
            #pragma unroll
            for (int j = 0; j < 8; ++j)
                #pragma unroll
                for (int i = 0; i < 8; ++i) a[j][i] += nr[j] * wr[i];
        }
    }

    float bb[8];
    #pragma unroll
    for (int i = 0; i < 8; ++i) {
        int o = oz + tx * 8 + i;
        bb[i] = which ? (__ldg(&b1[o]) + __ldg(&b2[o])) : 0.f;
    }
    float* dst = which ? g_baset : g_p1t;
    #pragma unroll
    for (int j = 0; j < 8; ++j) {
        int n = n0 + ty * 8 + j;
        int base = (b * Ndim + n) * Odim + oz + tx * 8;
        float4 v0 = {a[j][0] + bb[0], a[j][1] + bb[1], a[j][2] + bb[2], a[j][3] + bb[3]};
        float4 v1 = {a[j][4] + bb[4], a[j][5] + bb[5], a[j][6] + bb[6], a[j][7] + bb[7]};
        *(float4*)&dst[base]     = v0;
        *(float4*)&dst[base + 4] = v1;
    }
}

// ==============================================================================
// Kernel E: y[b,o,n] = relu(max_k (base[b,n,o] + p1t[b,idx[n,k],o]))
// ==============================================================================
__global__ __launch_bounds__(256) void k_edge(float* __restrict__ out) {
    __shared__ int   idxs[32][16];
    __shared__ float ys[32][257];

    const int b  = blockIdx.y;
    const int n0 = blockIdx.x * 32;
    const int tid = threadIdx.x;

    #pragma unroll
    for (int i = 0; i < 2; ++i) {
        int j = tid + i * 256;
        idxs[j >> 4][j & 15] = g_idx[(b * Ndim + n0 + (j >> 4)) * KNN + (j & 15)];
    }
    __syncthreads();

    #pragma unroll 1
    for (int nn = 0; nn < 32; ++nn) {
        float v = g_baset[(b * Ndim + n0 + nn) * Odim + tid];
        float acc = -FLT_MAX;
        #pragma unroll
        for (int t = 0; t < 16; ++t) {
            int m = idxs[nn][t];
            acc = fmaxf(acc, v + g_p1t[(b * Ndim + m) * Odim + tid]);
        }
        ys[nn][tid] = fmaxf(acc, 0.f);
    }
    __syncthreads();

    #pragma unroll
    for (int i = 0; i < 32; ++i) {
        int j = tid + i * 256;
        int o = j >> 5, n = j & 31;
        out[(b * Odim + o) * Ndim + n0 + n] = ys[n][o];
    }
}

// ==============================================================================
extern "C" void kernel_launch(void* const* d_in, const int* in_sizes, int n_in,
                              void* d_out, int out_size) {
    const float *x = 0, *w0 = 0, *b0 = 0, *w1 = 0, *b1 = 0, *w2 = 0, *b2 = 0;
    for (int i = 0; i < n_in; ++i) {
        const float* p = (const float*)d_in[i];
        switch (in_sizes[i]) {
            case 4194304: x = p; break;
            case 16384:   w0 = p; break;
            case 128:     b0 = p; break;
            case 32768:   if (!w1) w1 = p; else w2 = p; break;
            case 256:     if (!b1) b1 = p; else b2 = p; break;
            default: break; // k, scale scalars
        }
    }
    float* out = (float*)d_out;

    cudaFuncSetAttribute(k_knn, cudaFuncAttributeMaxDynamicSharedMemorySize, SM_TOT);

    k_net  <<<dim3(32, 8),        256>>>(x, w0, b0);
    k_split<<<dim3(128, 4, 8),    256>>>();
    k_knn  <<<dim3(32, 8),        256, SM_TOT>>>();
    k_resc <<<dim3(Ndim / 8, 8),  256>>>();
    k_proj <<<dim3(32, 8, 4),     256>>>(w1, b1, w2, b2);
    k_edge <<<dim3(128, 8),       256>>>(out);
}

// round 17
// speedup vs baseline: 23.8655x; 1.1036x over previous
#include <cuda_runtime.h>
#include <cuda_fp16.h>
#include <float.h>
#include <stdint.h>

#define Bsz  8
#define Cdim 128
#define Ndim 4096
#define Odim 256
#define KNN  16
#define NCAND 32
#define FULLM 0xFFFFFFFFu

// ---------------- scratch (static device globals; no allocations) -------------
__device__ float g_net[Bsz * Cdim * Ndim];     // [b][c][n]      16 MB
__device__ float g_sq[Bsz * Ndim];             // [b][n]
__device__ int   g_idx[Bsz * Ndim * KNN];      // [b][n][k]       2 MB
__device__ float g_p1t[Bsz * Ndim * Odim];     // [b][n][o]      32 MB
__device__ float g_baset[Bsz * Ndim * Odim];   // [b][n][o]      32 MB
__device__ __half g_hi[Bsz * Ndim * Cdim];     // [b][n][c]       8 MB
__device__ __half g_lo[Bsz * Ndim * Cdim];     // [b][n][c]       8 MB
__device__ float g_netT[Bsz * Ndim * Cdim];    // [b][n][c]      16 MB
__device__ int   g_cand[Bsz * Ndim * NCAND];   // coarse candidate indices
__device__ __half g_w1hi[Odim * Cdim];         // w1 hi            [o][c]
__device__ __half g_w1lo[Odim * Cdim];
__device__ __half g_wdhi[Odim * Cdim];         // (w2-w1) hi       [o][c]
__device__ __half g_wdlo[Odim * Cdim];

__device__ __forceinline__ uint32_t smem_u32(const void* p) {
    uint32_t a;
    asm("{ .reg .u64 t; cvta.to.shared.u64 t, %1; cvt.u32.u64 %0, t; }" : "=r"(a) : "l"(p));
    return a;
}
__device__ __forceinline__ void ldmx4(uint32_t* r, uint32_t addr) {
    asm volatile("ldmatrix.sync.aligned.m8n8.x4.shared.b16 {%0,%1,%2,%3}, [%4];"
        : "=r"(r[0]), "=r"(r[1]), "=r"(r[2]), "=r"(r[3]) : "r"(addr));
}
__device__ __forceinline__ void mma16816(float* c, const uint32_t* a,
                                         uint32_t b0, uint32_t b1) {
    asm volatile("mma.sync.aligned.m16n8k16.row.col.f32.f16.f16.f32 "
        "{%0,%1,%2,%3}, {%4,%5,%6,%7}, {%8,%9}, {%0,%1,%2,%3};"
        : "+f"(c[0]), "+f"(c[1]), "+f"(c[2]), "+f"(c[3])
        : "r"(a[0]), "r"(a[1]), "r"(a[2]), "r"(a[3]), "r"(b0), "r"(b1));
}

// ==============================================================================
// Kernel A: net = relu(w0 @ x + b0), fused sq[b][n] = sum_c net^2
// ==============================================================================
__global__ __launch_bounds__(256) void k_net(const float* __restrict__ x,
                                             const float* __restrict__ w0,
                                             const float* __restrict__ b0) {
    __shared__ float Ws[32][129];
    __shared__ float Ns[32][128];
    __shared__ float sqs[16][129];

    const int b  = blockIdx.y;
    const int n0 = blockIdx.x * 128;
    const int tid = threadIdx.x;
    const int tx = tid & 15;
    const int ty = tid >> 4;

    float acc[8][8];
    #pragma unroll
    for (int i = 0; i < 8; ++i)
        #pragma unroll
        for (int j = 0; j < 8; ++j) acc[i][j] = 0.f;

    for (int k0 = 0; k0 < 128; k0 += 32) {
        __syncthreads();
        #pragma unroll
        for (int i = 0; i < 16; ++i) {
            int idx = tid + i * 256;
            int cc = idx & 31, o = idx >> 5;
            Ws[cc][o] = w0[o * 128 + k0 + cc];
        }
        #pragma unroll
        for (int i = 0; i < 16; ++i) {
            int idx = tid + i * 256;
            int c = idx >> 7, n = idx & 127;
            Ns[c][n] = x[(b * 128 + k0 + c) * Ndim + n0 + n];
        }
        __syncthreads();
        #pragma unroll
        for (int kk = 0; kk < 32; ++kk) {
            float4 x0 = *(const float4*)&Ns[kk][tx * 8];
            float4 x1 = *(const float4*)&Ns[kk][tx * 8 + 4];
            float xr[8] = {x0.x, x0.y, x0.z, x0.w, x1.x, x1.y, x1.z, x1.w};
            #pragma unroll
            for (int i = 0; i < 8; ++i) {
                float wv = Ws[kk][ty * 8 + i];
                #pragma unroll
                for (int j = 0; j < 8; ++j) acc[i][j] += wv * xr[j];
            }
        }
    }

    float part[8];
    #pragma unroll
    for (int j = 0; j < 8; ++j) part[j] = 0.f;

    #pragma unroll
    for (int i = 0; i < 8; ++i) {
        int o = ty * 8 + i;
        float bv = __ldg(&b0[o]);
        float r[8];
        #pragma unroll
        for (int j = 0; j < 8; ++j) {
            r[j] = fmaxf(acc[i][j] + bv, 0.f);
            part[j] += r[j] * r[j];
        }
        int base = (b * 128 + o) * Ndim + n0 + tx * 8;
        float4 s0 = {r[0], r[1], r[2], r[3]};
        float4 s1 = {r[4], r[5], r[6], r[7]};
        *(float4*)&g_net[base]     = s0;
        *(float4*)&g_net[base + 4] = s1;
    }
    #pragma unroll
    for (int j = 0; j < 8; ++j) sqs[ty][tx * 8 + j] = part[j];
    __syncthreads();
    if (tid < 128) {
        float s = 0.f;
        #pragma unroll
        for (int r = 0; r < 16; ++r) s += sqs[r][tid];
        g_sq[b * Ndim + n0 + tid] = s;
    }
}

// ==============================================================================
// Kernel B: transpose: g_net[b][c][n] -> g_hi/g_lo (fp16 hi/lo) + g_netT (fp32)
// ==============================================================================
__global__ __launch_bounds__(256) void k_split() {
    __shared__ float s[32][33];
    const int b  = blockIdx.z;
    const int c0 = blockIdx.y * 32;
    const int n0 = blockIdx.x * 32;
    const int tx = threadIdx.x & 31;
    const int ty = threadIdx.x >> 5;    // 0..7

    #pragma unroll
    for (int i = 0; i < 4; ++i) {
        int c = ty + i * 8;
        s[c][tx] = g_net[(b * Cdim + c0 + c) * Ndim + n0 + tx];
    }
    __syncthreads();
    #pragma unroll
    for (int i = 0; i < 4; ++i) {
        int nl = ty + i * 8;
        float v = s[tx][nl];
        int dst = (b * Ndim + n0 + nl) * Cdim + c0 + tx;
        __half hi = __float2half(v);
        g_hi[dst]   = hi;
        g_lo[dst]   = __float2half(v - __half2float(hi));
        g_netT[dst] = v;
    }
}

// ==============================================================================
// Kernel B2: fp16 hi/lo split of w1 and (w2 - w1), [o][c] row-major.
// grid (256), 128 threads.
// ==============================================================================
__global__ __launch_bounds__(128) void k_wsplit(const float* __restrict__ w1,
                                                const float* __restrict__ w2) {
    const int o = blockIdx.x;
    const int c = threadIdx.x;
    const int i = o * Cdim + c;
    float v1 = w1[i];
    float vd = w2[i] - v1;
    __half h1 = __float2half(v1);
    __half hd = __float2half(vd);
    g_w1hi[i] = h1;
    g_w1lo[i] = __float2half(v1 - __half2float(h1));
    g_wdhi[i] = hd;
    g_wdlo[i] = __float2half(vd - __half2float(hd));
}

// ==============================================================================
// Kernel C v15 (UNCHANGED from 1033us build): coarse kNN, 1-pass fp16 gram,
// double-buffered M tiles, keys tile, 2 threads/query depth-16 register lists.
// ==============================================================================
#define PITCHB 272                     // 136 halves/row: conflict-free ldmatrix
#define TILEB  (128 * PITCHB)          // 34816 B per 128x128 fp16 tile
#define SM_QHI 0
#define SM_MH0 TILEB                   // M buffer 0
#define SM_MH1 (2 * TILEB)             // M buffer 1
#define SM_KEY (3 * TILEB)             // 128 x 132 floats = 67584 B
#define SM_SQ0 (SM_KEY + 128 * 132 * 4)
#define SM_SQ1 (SM_SQ0 + 512)
#define SM_TOT (SM_SQ1 + 512)          // 173568 B

__device__ __forceinline__ void load_tile16(char* smem, uint32_t dst,
                                            const __half* __restrict__ src) {
    for (int i = threadIdx.x; i < 2048; i += 256) {
        int row = i >> 4, c8 = (i & 15) * 8;
        uint4 v = *(const uint4*)(src + row * Cdim + c8);
        *(uint4*)(smem + dst + row * PITCHB + c8 * 2) = v;
    }
}

// Branchless sorted insert (registers, static indices). Caller: d < kd[15].
__device__ __forceinline__ void ins16(float (&kd)[16], int (&ki)[16],
                                      float d, int m) {
    int r = 0;
    #pragma unroll
    for (int i = 0; i < 16; ++i) r += (kd[i] <= d) ? 1 : 0;
    #pragma unroll
    for (int j = 15; j > 0; --j) {
        bool sh = (j > r);
        kd[j] = sh ? kd[j - 1] : kd[j];
        ki[j] = sh ? ki[j - 1] : ki[j];
    }
    #pragma unroll
    for (int j = 0; j < 16; ++j)
        if (j == r) { kd[j] = d; ki[j] = m; }
}

__global__ __launch_bounds__(256, 1) void k_knn() {
    extern __shared__ char smem[];
    const uint32_t sbase = smem_u32(smem);
    const int tid  = threadIdx.x;
    const int lane = tid & 31;
    const int wid  = tid >> 5;          // 0..7
    const int b    = blockIdx.y;
    const int n0   = blockIdx.x * 128;
    const int qbase = wid * 16;

    // Stage Q hi tile + first M tile
    load_tile16(smem, SM_QHI, g_hi + (size_t)(b * Ndim + n0) * Cdim);
    load_tile16(smem, SM_MH0, g_hi + (size_t)(b * Ndim) * Cdim);
    if (tid < 128) ((float*)(smem + SM_SQ0))[tid] = g_sq[b * Ndim + tid];
    __syncthreads();

    const uint32_t a_base = sbase + SM_QHI + (qbase + (lane & 15)) * PITCHB + ((lane >> 4) << 4);
    const uint32_t b_base0 = sbase + SM_MH0 + ((lane & 7) + ((lane >> 4) << 3)) * PITCHB
                                   + (((lane >> 3) & 1) << 4);

    float* keysp = (float*)(smem + SM_KEY);

    // scan identity: query (tid & 127), m-half (tid >> 7)
    const int sq_ = tid & 127;
    const int hf  = tid >> 7;

    float kd[16]; int ki[16];
    #pragma unroll
    for (int i = 0; i < 16; ++i) { kd[i] = FLT_MAX; ki[i] = 0; }
    float worst = FLT_MAX;

    for (int mt = 0; mt < 32; ++mt) {
        const int m0 = mt * 128;
        const int buf = mt & 1;
        const float* sqm = (const float*)(smem + SM_SQ0 + buf * 512);

        float c[16][4];
        #pragma unroll
        for (int t = 0; t < 16; ++t)
            #pragma unroll
            for (int e = 0; e < 4; ++e) c[t][e] = 0.f;

        const uint32_t bb = b_base0 + buf * TILEB;
        #pragma unroll
        for (int ks = 0; ks < 8; ++ks) {
            uint32_t ra[4];
            ldmx4(ra, a_base + ks * 32);
            #pragma unroll
            for (int tp = 0; tp < 8; ++tp) {
                uint32_t rb[4];
                ldmx4(rb, bb + tp * (16 * PITCHB) + ks * 32);
                mma16816(c[2 * tp],     ra, rb[0], rb[1]);
                mma16816(c[2 * tp + 1], ra, rb[2], rb[3]);
            }
        }

        // keys[q][m] = sq[m] - 2*dot  (unpacked, verified layout)
        const int q0 = qbase + (lane >> 2);
        const int mo = (lane & 3) * 2;
        #pragma unroll
        for (int t = 0; t < 16; ++t) {
            int m = t * 8 + mo;
            float s0 = sqm[m], s1 = sqm[m + 1];
            *(float2*)&keysp[q0 * 132 + m] =
                make_float2(s0 - 2.f * c[t][0], s1 - 2.f * c[t][1]);
            *(float2*)&keysp[(q0 + 8) * 132 + m] =
                make_float2(s0 - 2.f * c[t][2], s1 - 2.f * c[t][3]);
        }
        __syncthreads();   // keys visible; all reads of M[buf] complete

        // prefetch next M tile into the other buffer (overlaps with scan)
        if (mt < 31) {
            load_tile16(smem, SM_MH0 + (1 - buf) * TILEB,
                        g_hi + (size_t)(b * Ndim + m0 + 128) * Cdim);
            if (tid < 128)
                ((float*)(smem + SM_SQ0 + (1 - buf) * 512))[tid] =
                    g_sq[b * Ndim + m0 + 128 + tid];
        }

        // coarse scan: 2 threads per query, disjoint halves
        {
            const float* krow = keysp + sq_ * 132 + hf * 64;
            const int mbase = m0 + hf * 64;
            #pragma unroll 4
            for (int m = 0; m < 64; ++m) {
                float kv = krow[m];
                if (kv < worst) { ins16(kd, ki, kv, mbase + m); worst = kd[15]; }
            }
        }
        __syncthreads();   // scan done (keys free) AND next M tile resident
    }

    {
        int* crow = g_cand + ((size_t)(b * Ndim + n0 + sq_)) * NCAND + hf * 16;
        #pragma unroll
        for (int i = 0; i < 16; ++i) crow[i] = ki[i];
    }
}

// ==============================================================================
// Kernel C2 (UNCHANGED): exact fp32 rescore of 32 candidates + exact top-17.
// ==============================================================================
__global__ __launch_bounds__(256) void k_resc() {
    const int lane = threadIdx.x & 31;
    const int wid  = threadIdx.x >> 5;
    const int b    = blockIdx.y;
    const int q    = blockIdx.x * 8 + wid;

    const float4 qv = *(const float4*)&g_netT[(size_t)(b * Ndim + q) * Cdim + lane * 4];
    const int* crow = g_cand + ((size_t)(b * Ndim + q)) * NCAND;
    int ma = crow[lane];

    float part[NCAND];
    #pragma unroll
    for (int ci = 0; ci < NCAND; ++ci) {
        int m = __shfl_sync(FULLM, ma, ci);
        float4 mv = *(const float4*)&g_netT[(size_t)(b * Ndim + m) * Cdim + lane * 4];
        part[ci] = qv.x * mv.x + qv.y * mv.y + qv.z * mv.z + qv.w * mv.w;
    }
    #pragma unroll
    for (int ci = 0; ci < NCAND; ++ci) {
        float v = part[ci];
        v += __shfl_xor_sync(FULLM, v, 16);
        v += __shfl_xor_sync(FULLM, v, 8);
        v += __shfl_xor_sync(FULLM, v, 4);
        v += __shfl_xor_sync(FULLM, v, 2);
        v += __shfl_xor_sync(FULLM, v, 1);
        part[ci] = v;
    }
    float da = 0.f;
    #pragma unroll
    for (int ci = 0; ci < NCAND; ++ci) da = (lane == ci) ? part[ci] : da;

    float ka = __ldg(&g_sq[b * Ndim + ma]) - 2.f * da;

    int* orow = g_idx + ((size_t)(b * Ndim + q)) * KNN;
    #pragma unroll 1
    for (int t = 0; t < 17; ++t) {
        float lk = ka;
        int   lm = ma;
        #pragma unroll
        for (int d = 16; d > 0; d >>= 1) {
            float ok = __shfl_xor_sync(FULLM, lk, d);
            int   om = __shfl_xor_sync(FULLM, lm, d);
            bool take = (ok < lk) || (ok == lk && om < lm);
            lk = take ? ok : lk;
            lm = take ? om : lm;
        }
        if (t > 0 && lane == 0) orow[t - 1] = lm;   // t=0 = self (strict min) dropped
        if (ma == lm) ka = FLT_MAX;
    }
}

// ==============================================================================
// Kernel D v3: fp16 hi/lo tensor-core proj.
//   which=0: p1   = w1@net                  -> g_p1t  [b][n][o]
//   which=1: base = (w2-w1)@net + (b1+b2)   -> g_baset[b][n][o]
// A = net tiles [n][c] hi/lo (staged once); B = w tiles [o][c] hi/lo per stage.
// 3 passes: whi*nhi + wlo*nhi + whi*nlo (fp32 accum).
// grid (32 n-tiles, 8 b), 256 threads (8 warps; warp owns 16 n-rows).
// ==============================================================================
#define P_AHI 0
#define P_ALO TILEB
#define P_BHI (2 * TILEB)
#define P_BLO (3 * TILEB)
#define P_BS  (4 * TILEB)              // bias sums: 256 floats
#define P_TOT (P_BS + 1024)            // 140288 B

__global__ __launch_bounds__(256, 1) void k_proj_f16(const float* __restrict__ b1,
                                                     const float* __restrict__ b2) {
    extern __shared__ char smem[];
    const uint32_t sbase = smem_u32(smem);
    const int tid  = threadIdx.x;
    const int lane = tid & 31;
    const int wid  = tid >> 5;
    const int b    = blockIdx.y;
    const int n0   = blockIdx.x * 128;
    const int qbase = wid * 16;

    // Stage A (net) tiles once + bias sums
    load_tile16(smem, P_AHI, g_hi + (size_t)(b * Ndim + n0) * Cdim);
    load_tile16(smem, P_ALO, g_lo + (size_t)(b * Ndim + n0) * Cdim);
    if (tid < 256) ((float*)(smem + P_BS))[tid] = __ldg(&b1[tid]) + __ldg(&b2[tid]);

    // fragment addresses (identical formulas to verified k_knn)
    const uint32_t a_base = sbase + P_AHI + (qbase + (lane & 15)) * PITCHB + ((lane >> 4) << 4);
    const uint32_t b_base = sbase + P_BHI + ((lane & 7) + ((lane >> 4) << 3)) * PITCHB
                                  + (((lane >> 3) & 1) << 4);
    const float* bsum = (const float*)(smem + P_BS);

    #pragma unroll 1
    for (int s = 0; s < 4; ++s) {
        const int which = s >> 1;
        const int oh    = s & 1;
        __syncthreads();   // previous stage's B reads done; bias/A ready (s=0)
        {
            const __half* bhsrc = (which ? g_wdhi : g_w1hi) + oh * 128 * Cdim;
            const __half* blsrc = (which ? g_wdlo : g_w1lo) + oh * 128 * Cdim;
            load_tile16(smem, P_BHI, bhsrc);
            load_tile16(smem, P_BLO, blsrc);
        }
        __syncthreads();

        float c[16][4];
        #pragma unroll
        for (int t = 0; t < 16; ++t)
            #pragma unroll
            for (int e = 0; e < 4; ++e) c[t][e] = 0.f;

        #pragma unroll 1
        for (int pass = 0; pass < 3; ++pass) {
            const uint32_t ab = a_base + (pass == 1 ? (P_ALO - P_AHI) : 0);
            const uint32_t bbb = b_base + (pass == 2 ? (P_BLO - P_BHI) : 0);
            #pragma unroll
            for (int ks = 0; ks < 8; ++ks) {
                uint32_t ra[4];
                ldmx4(ra, ab + ks * 32);
                #pragma unroll
                for (int tp = 0; tp < 8; ++tp) {
                    uint32_t rb[4];
                    ldmx4(rb, bbb + tp * (16 * PITCHB) + ks * 32);
                    mma16816(c[2 * tp],     ra, rb[0], rb[1]);
                    mma16816(c[2 * tp + 1], ra, rb[2], rb[3]);
                }
            }
        }

        // epilogue: rows = n (local), cols = o (local); write [b][n][o] float2
        const int nr0 = qbase + (lane >> 2);
        const int mo  = (lane & 3) * 2;
        float* dst = which ? g_baset : g_p1t;
        #pragma unroll
        for (int t = 0; t < 16; ++t) {
            int ol = t * 8 + mo;                 // local o in [0,128)
            int o  = oh * 128 + ol;
            float bb0 = which ? bsum[o]     : 0.f;
            float bb1 = which ? bsum[o + 1] : 0.f;
            size_t a0 = ((size_t)(b * Ndim + n0 + nr0)) * Odim + o;
            size_t a1 = ((size_t)(b * Ndim + n0 + nr0 + 8)) * Odim + o;
            *(float2*)&dst[a0] = make_float2(c[t][0] + bb0, c[t][1] + bb1);
            *(float2*)&dst[a1] = make_float2(c[t][2] + bb0, c[t][3] + bb1);
        }
    }
}

// ==============================================================================
// Kernel E: y[b,o,n] = relu(max_k (base[b,n,o] + p1t[b,idx[n,k],o]))
// ==============================================================================
__global__ __launch_bounds__(256) void k_edge(float* __restrict__ out) {
    __shared__ int   idxs[32][16];
    __shared__ float ys[32][257];

    const int b  = blockIdx.y;
    const int n0 = blockIdx.x * 32;
    const int tid = threadIdx.x;

    #pragma unroll
    for (int i = 0; i < 2; ++i) {
        int j = tid + i * 256;
        idxs[j >> 4][j & 15] = g_idx[(b * Ndim + n0 + (j >> 4)) * KNN + (j & 15)];
    }
    __syncthreads();

    #pragma unroll 1
    for (int nn = 0; nn < 32; ++nn) {
        float v = g_baset[(b * Ndim + n0 + nn) * Odim + tid];
        float acc = -FLT_MAX;
        #pragma unroll
        for (int t = 0; t < 16; ++t) {
            int m = idxs[nn][t];
            acc = fmaxf(acc, v + g_p1t[(b * Ndim + m) * Odim + tid]);
        }
        ys[nn][tid] = fmaxf(acc, 0.f);
    }
    __syncthreads();

    #pragma unroll
    for (int i = 0; i < 32; ++i) {
        int j = tid + i * 256;
        int o = j >> 5, n = j & 31;
        out[(b * Odim + o) * Ndim + n0 + n] = ys[n][o];
    }
}

// ==============================================================================
extern "C" void kernel_launch(void* const* d_in, const int* in_sizes, int n_in,
                              void* d_out, int out_size) {
    const float *x = 0, *w0 = 0, *b0 = 0, *w1 = 0, *b1 = 0, *w2 = 0, *b2 = 0;
    for (int i = 0; i < n_in; ++i) {
        const float* p = (const float*)d_in[i];
        switch (in_sizes[i]) {
            case 4194304: x = p; break;
            case 16384:   w0 = p; break;
            case 128:     b0 = p; break;
            case 32768:   if (!w1) w1 = p; else w2 = p; break;
            case 256:     if (!b1) b1 = p; else b2 = p; break;
            default: break; // k, scale scalars
        }
    }
    float* out = (float*)d_out;

    cudaFuncSetAttribute(k_knn, cudaFuncAttributeMaxDynamicSharedMemorySize, SM_TOT);
    cudaFuncSetAttribute(k_proj_f16, cudaFuncAttributeMaxDynamicSharedMemorySize, P_TOT);

    k_net     <<<dim3(32, 8),       256>>>(x, w0, b0);
    k_wsplit  <<<dim3(256),         128>>>(w1, w2);
    k_split   <<<dim3(128, 4, 8),   256>>>();
    k_knn     <<<dim3(32, 8),       256, SM_TOT>>>();
    k_resc    <<<dim3(Ndim / 8, 8), 256>>>();
    k_proj_f16<<<dim3(32, 8),       256, P_TOT>>>(b1, b2);
    k_edge    <<<dim3(128, 8),      256>>>(out);
}